// round 1
// baseline (speedup 1.0000x reference)
#include <cuda_runtime.h>
#include <math.h>

#define NMAX 100000
#define HDIM 128
#define EMAX 625000
#define NEG_SLOPE 0.2f

// ---------------- scratch (device globals; no runtime allocation) -------------
__device__ float g_xs[NMAX * HDIM];     // source transform  x@Wl+bl
__device__ float g_xd[NMAX * HDIM];     // target transform  x@Wr+br
__device__ float g_acc[NMAX * HDIM];    // scatter accumulator -> h1 -> out2 (in place)
__device__ float g_x[NMAX * HDIM];      // activations between layers
__device__ float g_logits[EMAX];
__device__ float g_m[NMAX];
__device__ float g_denom[NMAX];
__device__ float g_sum[HDIM];
__device__ float g_sumsq[HDIM];

// ---------------- helpers ------------------------------------------------------
__device__ __forceinline__ void atomicMaxFloat(float* addr, float val) {
    if (val >= 0.0f) atomicMax((int*)addr, __float_as_int(val));
    else             atomicMin((unsigned int*)addr, __float_as_uint(val));
}

// ---------------- reset per layer ---------------------------------------------
__global__ void reset_kernel(int n) {
    int i = blockIdx.x * blockDim.x + threadIdx.x;
    int total = n * HDIM;
    if (i < total) g_acc[i] = 0.0f;
    if (i < n) { g_m[i] = __int_as_float(0xFF800000); g_denom[i] = 0.0f; }
    if (i < HDIM) { g_sum[i] = 0.0f; g_sumsq[i] = 0.0f; }
}

// ---------------- GEMM: Y = (residual? X : 0) + X @ W + bias -------------------
// X: [n,128], W: [128,128] row-major (k-major), Y: [n,128]. In-place (X==Y) safe:
// each block stages its own rows to smem before writing them.
__global__ __launch_bounds__(256) void gemm128_kernel(
    const float* __restrict__ X, const float* __restrict__ W,
    const float* __restrict__ bias, float* __restrict__ Y, int n, int residual)
{
    __shared__ float sW[64][128];   // 32 KB
    __shared__ float sx[64][64];    // 16 KB
    const int tid = threadIdx.x;
    const int tx = tid & 31;        // column group (cols tx*4 .. tx*4+3)
    const int ty = tid >> 5;        // row group (rows ty*8 .. ty*8+7)
    const int row0 = blockIdx.x * 64;

    float acc[8][4];
#pragma unroll
    for (int r = 0; r < 8; r++)
#pragma unroll
        for (int c = 0; c < 4; c++) acc[r][c] = 0.0f;

    for (int k0 = 0; k0 < 128; k0 += 64) {
        // load W chunk [64,128]
        for (int t = tid; t < 64 * 32; t += 256) {
            int r = t >> 5, c = (t & 31) * 4;
            *(float4*)&sW[r][c] = *(const float4*)&W[(k0 + r) * 128 + c];
        }
        // load x tile [64,64]
        for (int t = tid; t < 64 * 16; t += 256) {
            int r = t >> 4, c = (t & 15) * 4;
            int gr = row0 + r;
            float4 v = make_float4(0.f, 0.f, 0.f, 0.f);
            if (gr < n) v = *(const float4*)&X[(size_t)gr * 128 + k0 + c];
            *(float4*)&sx[r][c] = v;
        }
        __syncthreads();

#pragma unroll
        for (int k = 0; k < 64; k += 4) {
            float4 w0 = *(float4*)&sW[k + 0][tx * 4];
            float4 w1 = *(float4*)&sW[k + 1][tx * 4];
            float4 w2 = *(float4*)&sW[k + 2][tx * 4];
            float4 w3 = *(float4*)&sW[k + 3][tx * 4];
#pragma unroll
            for (int r = 0; r < 8; r++) {
                float4 a = *(float4*)&sx[ty * 8 + r][k];
                acc[r][0] = fmaf(a.x, w0.x, fmaf(a.y, w1.x, fmaf(a.z, w2.x, fmaf(a.w, w3.x, acc[r][0]))));
                acc[r][1] = fmaf(a.x, w0.y, fmaf(a.y, w1.y, fmaf(a.z, w2.y, fmaf(a.w, w3.y, acc[r][1]))));
                acc[r][2] = fmaf(a.x, w0.z, fmaf(a.y, w1.z, fmaf(a.z, w2.z, fmaf(a.w, w3.z, acc[r][2]))));
                acc[r][3] = fmaf(a.x, w0.w, fmaf(a.y, w1.w, fmaf(a.z, w2.w, fmaf(a.w, w3.w, acc[r][3]))));
            }
        }
        __syncthreads();
    }

    float4 b4 = *(const float4*)&bias[tx * 4];
#pragma unroll
    for (int r = 0; r < 8; r++) {
        int gr = row0 + ty * 8 + r;
        if (gr < n) {
            float4 o;
            o.x = acc[r][0] + b4.x; o.y = acc[r][1] + b4.y;
            o.z = acc[r][2] + b4.z; o.w = acc[r][3] + b4.w;
            if (residual) {
                float4 res = *(const float4*)&X[(size_t)gr * 128 + tx * 4];
                o.x += res.x; o.y += res.y; o.z += res.z; o.w += res.w;
            }
            *(float4*)&Y[(size_t)gr * 128 + tx * 4] = o;
        }
    }
}

// ---------------- edge pass 1: logits + segment max ----------------------------
__global__ __launch_bounds__(256) void edge_logits_kernel(
    const int* __restrict__ src, const int* __restrict__ dst,
    const float* __restrict__ att, int E)
{
    int w = (blockIdx.x * blockDim.x + threadIdx.x) >> 5;
    int lane = threadIdx.x & 31;
    if (w >= E) return;
    int s = src[w], d = dst[w];
    float4 a = *(const float4*)&g_xs[(size_t)s * 128 + lane * 4];
    float4 b = *(const float4*)&g_xd[(size_t)d * 128 + lane * 4];
    float4 at = *(const float4*)&att[lane * 4];
    float t, sum = 0.0f;
    t = a.x + b.x; t = t > 0.f ? t : NEG_SLOPE * t; sum = fmaf(t, at.x, sum);
    t = a.y + b.y; t = t > 0.f ? t : NEG_SLOPE * t; sum = fmaf(t, at.y, sum);
    t = a.z + b.z; t = t > 0.f ? t : NEG_SLOPE * t; sum = fmaf(t, at.z, sum);
    t = a.w + b.w; t = t > 0.f ? t : NEG_SLOPE * t; sum = fmaf(t, at.w, sum);
#pragma unroll
    for (int o = 16; o; o >>= 1) sum += __shfl_xor_sync(0xffffffff, sum, o);
    if (lane == 0) {
        g_logits[w] = sum;
        atomicMaxFloat(&g_m[d], sum);
    }
}

// ---------------- edge pass 2: exp, denom, weighted scatter --------------------
__global__ __launch_bounds__(256) void edge_scatter_kernel(
    const int* __restrict__ src, const int* __restrict__ dst, int E)
{
    int w = (blockIdx.x * blockDim.x + threadIdx.x) >> 5;
    int lane = threadIdx.x & 31;
    if (w >= E) return;
    int s = src[w], d = dst[w];
    float a = __expf(g_logits[w] - g_m[d]);
    if (lane == 0) atomicAdd(&g_denom[d], a);
    float4 xs4 = *(const float4*)&g_xs[(size_t)s * 128 + lane * 4];
    size_t base = (size_t)d * 128 + lane * 4;
    atomicAdd(&g_acc[base + 0], a * xs4.x);
    atomicAdd(&g_acc[base + 1], a * xs4.y);
    atomicAdd(&g_acc[base + 2], a * xs4.z);
    atomicAdd(&g_acc[base + 3], a * xs4.w);
}

// ---------------- node finish: out = acc/denom + cb ----------------------------
__global__ __launch_bounds__(256) void node_finish_kernel(const float* __restrict__ cb, int n)
{
    int i = blockIdx.x * blockDim.x + threadIdx.x;
    if (i >= n * HDIM) return;
    int node = i >> 7, h = i & 127;
    g_acc[i] = g_acc[i] / (g_denom[node] + 1e-16f) + cb[h];
}

// ---------------- BN stats: per-column sum / sumsq -----------------------------
__global__ __launch_bounds__(128) void bn_stats_kernel(int n)
{
    int h = threadIdx.x;
    int rows_per = (n + gridDim.x - 1) / gridDim.x;
    int r0 = blockIdx.x * rows_per;
    int r1 = min(n, r0 + rows_per);
    float s = 0.0f, sq = 0.0f;
    for (int r = r0; r < r1; r++) {
        float v = g_acc[(size_t)r * 128 + h];
        s += v; sq += v * v;
    }
    atomicAdd(&g_sum[h], s);
    atomicAdd(&g_sumsq[h], sq);
}

// ---------------- BN apply (+ optional relu) ------------------------------------
__global__ __launch_bounds__(256) void bn_apply_kernel(
    const float* __restrict__ gamma, const float* __restrict__ beta,
    float* __restrict__ out, int n, int do_relu)
{
    int i = blockIdx.x * blockDim.x + threadIdx.x;
    if (i >= n * HDIM) return;
    int h = i & 127;
    float inv_n = 1.0f / (float)n;
    float mu = g_sum[h] * inv_n;
    float var = g_sumsq[h] * inv_n - mu * mu;
    float v = (g_acc[i] - mu) * rsqrtf(var + 1e-5f) * gamma[h] + beta[h];
    if (do_relu) v = fmaxf(v, 0.0f);
    out[i] = v;
}

// ---------------- host driver ---------------------------------------------------
extern "C" void kernel_launch(void* const* d_in, const int* in_sizes, int n_in,
                              void* d_out, int out_size)
{
    const float* x     = (const float*)d_in[0];
    const int*   ei    = (const int*)  d_in[1];
    const float* Wl    = (const float*)d_in[2];
    const float* bl    = (const float*)d_in[3];
    const float* Wr    = (const float*)d_in[4];
    const float* br    = (const float*)d_in[5];
    const float* att   = (const float*)d_in[6];
    const float* cb    = (const float*)d_in[7];
    const float* Wlin  = (const float*)d_in[8];
    const float* blin  = (const float*)d_in[9];
    const float* gamma = (const float*)d_in[10];
    const float* beta  = (const float*)d_in[11];

    const int n = in_sizes[0] / HDIM;
    const int E = in_sizes[1] / 2;
    const int* src = ei;
    const int* dst = ei + E;

    void* p;
    cudaGetSymbolAddress(&p, g_xs);  float* p_xs  = (float*)p;
    cudaGetSymbolAddress(&p, g_xd);  float* p_xd  = (float*)p;
    cudaGetSymbolAddress(&p, g_acc); float* p_acc = (float*)p;
    cudaGetSymbolAddress(&p, g_x);   float* p_x   = (float*)p;

    const int elem_blocks = (n * HDIM + 255) / 256;
    const int gemm_blocks = (n + 63) / 64;
    const int edge_blocks = (E * 32 + 255) / 256;  // 1 warp per edge

    for (int layer = 0; layer < 2; layer++) {
        const float* xin = (layer == 0) ? x : p_x;
        const float* Wl_i   = Wl   + (size_t)layer * HDIM * HDIM;
        const float* bl_i   = bl   + layer * HDIM;
        const float* Wr_i   = Wr   + (size_t)layer * HDIM * HDIM;
        const float* br_i   = br   + layer * HDIM;
        const float* att_i  = att  + layer * HDIM;
        const float* cb_i   = cb   + layer * HDIM;
        const float* Wlin_i = Wlin + (size_t)layer * HDIM * HDIM;
        const float* blin_i = blin + layer * HDIM;
        const float* g_i    = gamma + layer * HDIM;
        const float* b_i    = beta  + layer * HDIM;

        reset_kernel<<<elem_blocks, 256>>>(n);
        gemm128_kernel<<<gemm_blocks, 256>>>(xin, Wl_i, bl_i, p_xs, n, 0);
        gemm128_kernel<<<gemm_blocks, 256>>>(xin, Wr_i, br_i, p_xd, n, 0);
        edge_logits_kernel<<<edge_blocks, 256>>>(src, dst, att_i, E);
        edge_scatter_kernel<<<edge_blocks, 256>>>(src, dst, E);
        node_finish_kernel<<<elem_blocks, 256>>>(cb_i, n);
        gemm128_kernel<<<gemm_blocks, 256>>>(p_acc, Wlin_i, blin_i, p_acc, n, 1);
        bn_stats_kernel<<<256, 128>>>(n);
        bn_apply_kernel<<<elem_blocks, 256>>>(g_i, b_i,
            (layer == 0) ? p_x : (float*)d_out, n, (layer == 0) ? 1 : 0);
    }
}

// round 2
// speedup vs baseline: 1.3517x; 1.3517x over previous
#include <cuda_runtime.h>
#include <math.h>

#define NMAX 100000
#define HDIM 128
#define EMAX 625000
#define NEG_SLOPE 0.2f

// ---------------- scratch (device globals; no runtime allocation) -------------
__device__ float g_xs[NMAX * HDIM];     // source transform  x@Wl+bl
__device__ float g_xd[NMAX * HDIM];     // target transform  x@Wr+br
__device__ float g_acc[NMAX * HDIM];    // aggregated h -> residual gemm in place
__device__ float g_x[NMAX * HDIM];      // activations between layers
__device__ float g_sum[HDIM];
__device__ float g_sumsq[HDIM];

// CSR scratch
__device__ int g_deg[NMAX];
__device__ int g_fill[NMAX];
__device__ int g_rowptr[NMAX + 1];
__device__ int g_col[EMAX];
__device__ int g_blocksum[128];

// ---------------- f32x2 helpers -------------------------------------------------
__device__ __forceinline__ unsigned long long pack_dup(float a) {
    unsigned long long r;
    unsigned int u = __float_as_uint(a);
    asm("mov.b64 %0, {%1, %1};" : "=l"(r) : "r"(u));
    return r;
}
__device__ __forceinline__ void ffma2(unsigned long long& d, unsigned long long a,
                                      unsigned long long b) {
    asm("fma.rn.f32x2 %0, %1, %2, %0;" : "+l"(d) : "l"(a), "l"(b));
}
__device__ __forceinline__ void unpack2(unsigned long long v, float& lo, float& hi) {
    unsigned int a, b;
    asm("mov.b64 {%0, %1}, %2;" : "=r"(a), "=r"(b) : "l"(v));
    lo = __uint_as_float(a); hi = __uint_as_float(b);
}

// ---------------- CSR build ------------------------------------------------------
__global__ void csr_zero_kernel(int n) {
    int i = blockIdx.x * blockDim.x + threadIdx.x;
    if (i < n) { g_deg[i] = 0; g_fill[i] = 0; }
}
__global__ void csr_hist_kernel(const int* __restrict__ dst, int E) {
    int e = blockIdx.x * blockDim.x + threadIdx.x;
    if (e < E) atomicAdd(&g_deg[dst[e]], 1);
}
__global__ void csr_scanA_kernel(int n) {
    __shared__ int s[1024];
    int t = threadIdx.x;
    int i = blockIdx.x * 1024 + t;
    int v = (i < n) ? g_deg[i] : 0;
    s[t] = v;
    __syncthreads();
#pragma unroll
    for (int off = 1; off < 1024; off <<= 1) {
        int x = (t >= off) ? s[t - off] : 0;
        __syncthreads();
        s[t] += x;
        __syncthreads();
    }
    if (i < n) g_rowptr[i + 1] = s[t];
    if (t == 1023) g_blocksum[blockIdx.x] = s[t];
    if (i == 0) g_rowptr[0] = 0;
}
__global__ void csr_scanB_kernel(int nb) {
    if (threadIdx.x == 0) {
        int run = 0;
        for (int i = 0; i < nb; i++) { int v = g_blocksum[i]; g_blocksum[i] = run; run += v; }
    }
}
__global__ void csr_scanC_kernel(int n) {
    int i = blockIdx.x * 1024 + threadIdx.x;
    if (i < n) g_rowptr[i + 1] += g_blocksum[blockIdx.x];
}
__global__ void csr_fill_kernel(const int* __restrict__ src, const int* __restrict__ dst, int E) {
    int e = blockIdx.x * blockDim.x + threadIdx.x;
    if (e < E) {
        int d = dst[e];
        int pos = g_rowptr[d] + atomicAdd(&g_fill[d], 1);
        g_col[pos] = src[e];
    }
}

// ---------------- GEMM v2: Y = (residual? X : 0) + X @ W + bias ------------------
// 128x128 tile / block, 256 threads, 8x8 per thread, FFMA2 packed fp32.
// In-place (X==Y) safe: block reads only its own rows; writes after all reads.
__global__ __launch_bounds__(256) void gemm128v2_kernel(
    const float* __restrict__ X, const float* __restrict__ W,
    const float* __restrict__ bias, float* __restrict__ Y, int n, int residual)
{
    __shared__ float sW[32][128];        // 16 KB per k-chunk
    __shared__ float sx[128][36];        // 18 KB (pad 4 -> 144B rows, 16B aligned)

    const int tid = threadIdx.x;
    const int cg = tid & 15;             // column group: cols cg*8 .. cg*8+7
    const int rg = tid >> 4;             // row group:    rows rg*8 .. rg*8+7
    const int row0 = blockIdx.x * 128;

    unsigned long long acc[8][4];
#pragma unroll
    for (int r = 0; r < 8; r++)
#pragma unroll
        for (int c = 0; c < 4; c++) acc[r][c] = 0ull;

    for (int k0 = 0; k0 < 128; k0 += 32) {
        // load W chunk [32][128]
#pragma unroll
        for (int i = 0; i < 4; i++) {
            int f = tid + i * 256;       // 1024 float4s
            int r = f >> 5, c = (f & 31) * 4;
            *(float4*)&sW[r][c] = *(const float4*)&W[(k0 + r) * 128 + c];
        }
        // load x chunk [128][32]
#pragma unroll
        for (int i = 0; i < 4; i++) {
            int f = tid + i * 256;       // 1024 float4s
            int r = f >> 3, c = (f & 7) * 4;
            int gr = row0 + r;
            float4 v = make_float4(0.f, 0.f, 0.f, 0.f);
            if (gr < n) v = *(const float4*)&X[(size_t)gr * 128 + k0 + c];
            *(float4*)&sx[r][c] = v;
        }
        __syncthreads();

#pragma unroll 4
        for (int k = 0; k < 32; k++) {
            const unsigned long long* wp = (const unsigned long long*)&sW[k][cg * 8];
            unsigned long long w0 = wp[0], w1 = wp[1], w2 = wp[2], w3 = wp[3];
#pragma unroll
            for (int r = 0; r < 8; r++) {
                unsigned long long ad = pack_dup(sx[rg * 8 + r][k]);
                ffma2(acc[r][0], ad, w0);
                ffma2(acc[r][1], ad, w1);
                ffma2(acc[r][2], ad, w2);
                ffma2(acc[r][3], ad, w3);
            }
        }
        __syncthreads();
    }

    float4 b0 = *(const float4*)&bias[cg * 8];
    float4 b1 = *(const float4*)&bias[cg * 8 + 4];
#pragma unroll
    for (int r = 0; r < 8; r++) {
        int gr = row0 + rg * 8 + r;
        if (gr >= n) continue;
        float4 o0, o1;
        unpack2(acc[r][0], o0.x, o0.y);
        unpack2(acc[r][1], o0.z, o0.w);
        unpack2(acc[r][2], o1.x, o1.y);
        unpack2(acc[r][3], o1.z, o1.w);
        o0.x += b0.x; o0.y += b0.y; o0.z += b0.z; o0.w += b0.w;
        o1.x += b1.x; o1.y += b1.y; o1.z += b1.z; o1.w += b1.w;
        if (residual) {
            float4 r0 = *(const float4*)&X[(size_t)gr * 128 + cg * 8];
            float4 r1 = *(const float4*)&X[(size_t)gr * 128 + cg * 8 + 4];
            o0.x += r0.x; o0.y += r0.y; o0.z += r0.z; o0.w += r0.w;
            o1.x += r1.x; o1.y += r1.y; o1.z += r1.z; o1.w += r1.w;
        }
        *(float4*)&Y[(size_t)gr * 128 + cg * 8] = o0;
        *(float4*)&Y[(size_t)gr * 128 + cg * 8 + 4] = o1;
    }
}

// ---------------- aggregation: one warp per node, online softmax ------------------
__global__ __launch_bounds__(256) void agg_kernel(
    const float* __restrict__ att, const float* __restrict__ cb, int n)
{
    // opportunistically zero BN accumulators for this layer
    if (blockIdx.x == 0 && threadIdx.x < HDIM) {
        g_sum[threadIdx.x] = 0.0f;
        g_sumsq[threadIdx.x] = 0.0f;
    }
    int d = (blockIdx.x * blockDim.x + threadIdx.x) >> 5;
    int lane = threadIdx.x & 31;
    if (d >= n) return;

    float4 xd4 = *(const float4*)&g_xd[(size_t)d * 128 + lane * 4];
    float4 at4 = *(const float4*)&att[lane * 4];
    int e0 = g_rowptr[d], e1 = g_rowptr[d + 1];

    float m = -INFINITY, den = 0.0f;
    float4 acc = make_float4(0.f, 0.f, 0.f, 0.f);

    for (int e = e0; e < e1; e++) {
        int s = g_col[e];
        float4 xs4 = *(const float4*)&g_xs[(size_t)s * 128 + lane * 4];
        float t, p = 0.0f;
        t = xs4.x + xd4.x; t = t > 0.f ? t : NEG_SLOPE * t; p = fmaf(t, at4.x, p);
        t = xs4.y + xd4.y; t = t > 0.f ? t : NEG_SLOPE * t; p = fmaf(t, at4.y, p);
        t = xs4.z + xd4.z; t = t > 0.f ? t : NEG_SLOPE * t; p = fmaf(t, at4.z, p);
        t = xs4.w + xd4.w; t = t > 0.f ? t : NEG_SLOPE * t; p = fmaf(t, at4.w, p);
#pragma unroll
        for (int o = 16; o; o >>= 1) p += __shfl_xor_sync(0xffffffff, p, o);
        // online softmax (exact max, numerically equivalent to reference)
        float mn = fmaxf(m, p);
        float co = __expf(m - mn);   // m=-inf first iter -> 0
        float w = __expf(p - mn);
        den = den * co + w;
        acc.x = fmaf(acc.x, co, w * xs4.x);
        acc.y = fmaf(acc.y, co, w * xs4.y);
        acc.z = fmaf(acc.z, co, w * xs4.z);
        acc.w = fmaf(acc.w, co, w * xs4.w);
        m = mn;
    }

    float inv = 1.0f / (den + 1e-16f);
    float4 cb4 = *(const float4*)&cb[lane * 4];
    float4 o;
    o.x = acc.x * inv + cb4.x;
    o.y = acc.y * inv + cb4.y;
    o.z = acc.z * inv + cb4.z;
    o.w = acc.w * inv + cb4.w;
    *(float4*)&g_acc[(size_t)d * 128 + lane * 4] = o;
}

// ---------------- BN stats: per-column sum / sumsq --------------------------------
__global__ __launch_bounds__(128) void bn_stats_kernel(int n)
{
    int h = threadIdx.x;
    float s = 0.0f, sq = 0.0f;
    for (int r = blockIdx.x; r < n; r += gridDim.x) {
        float v = g_acc[(size_t)r * 128 + h];
        s += v; sq += v * v;
    }
    atomicAdd(&g_sum[h], s);
    atomicAdd(&g_sumsq[h], sq);
}

// ---------------- BN apply (+ optional relu) ---------------------------------------
__global__ __launch_bounds__(256) void bn_apply_kernel(
    const float* __restrict__ gamma, const float* __restrict__ beta,
    float* __restrict__ out, int n, int do_relu)
{
    int i = blockIdx.x * blockDim.x + threadIdx.x;
    if (i >= n * HDIM) return;
    int h = i & 127;
    float inv_n = 1.0f / (float)n;
    float mu = g_sum[h] * inv_n;
    float var = g_sumsq[h] * inv_n - mu * mu;
    float v = (g_acc[i] - mu) * rsqrtf(var + 1e-5f) * gamma[h] + beta[h];
    if (do_relu) v = fmaxf(v, 0.0f);
    out[i] = v;
}

// ---------------- host driver -------------------------------------------------------
extern "C" void kernel_launch(void* const* d_in, const int* in_sizes, int n_in,
                              void* d_out, int out_size)
{
    const float* x     = (const float*)d_in[0];
    const int*   ei    = (const int*)  d_in[1];
    const float* Wl    = (const float*)d_in[2];
    const float* bl    = (const float*)d_in[3];
    const float* Wr    = (const float*)d_in[4];
    const float* br    = (const float*)d_in[5];
    const float* att   = (const float*)d_in[6];
    const float* cb    = (const float*)d_in[7];
    const float* Wlin  = (const float*)d_in[8];
    const float* blin  = (const float*)d_in[9];
    const float* gamma = (const float*)d_in[10];
    const float* beta  = (const float*)d_in[11];

    const int n = in_sizes[0] / HDIM;
    const int E = in_sizes[1] / 2;
    const int* src = ei;
    const int* dst = ei + E;

    void* p;
    cudaGetSymbolAddress(&p, g_xs);  float* p_xs  = (float*)p;
    cudaGetSymbolAddress(&p, g_xd);  float* p_xd  = (float*)p;
    cudaGetSymbolAddress(&p, g_acc); float* p_acc = (float*)p;
    cudaGetSymbolAddress(&p, g_x);   float* p_x   = (float*)p;

    const int elem_blocks = (n * HDIM + 255) / 256;
    const int gemm_blocks = (n + 127) / 128;
    const int agg_blocks  = (n + 7) / 8;          // 8 warps per block
    const int e_blocks    = (E + 255) / 256;
    const int scan_blocks = (n + 1023) / 1024;

    // --- CSR build (once per call; same for both layers) ---
    csr_zero_kernel<<<(n + 255) / 256, 256>>>(n);
    csr_hist_kernel<<<e_blocks, 256>>>(dst, E);
    csr_scanA_kernel<<<scan_blocks, 1024>>>(n);
    csr_scanB_kernel<<<1, 32>>>(scan_blocks);
    csr_scanC_kernel<<<scan_blocks, 1024>>>(n);
    csr_fill_kernel<<<e_blocks, 256>>>(src, dst, E);

    for (int layer = 0; layer < 2; layer++) {
        const float* xin = (layer == 0) ? x : p_x;
        const float* Wl_i   = Wl   + (size_t)layer * HDIM * HDIM;
        const float* bl_i   = bl   + layer * HDIM;
        const float* Wr_i   = Wr   + (size_t)layer * HDIM * HDIM;
        const float* br_i   = br   + layer * HDIM;
        const float* att_i  = att  + layer * HDIM;
        const float* cb_i   = cb   + layer * HDIM;
        const float* Wlin_i = Wlin + (size_t)layer * HDIM * HDIM;
        const float* blin_i = blin + layer * HDIM;
        const float* g_i    = gamma + layer * HDIM;
        const float* b_i    = beta  + layer * HDIM;

        gemm128v2_kernel<<<gemm_blocks, 256>>>(xin, Wl_i, bl_i, p_xs, n, 0);
        gemm128v2_kernel<<<gemm_blocks, 256>>>(xin, Wr_i, br_i, p_xd, n, 0);
        agg_kernel<<<agg_blocks, 256>>>(att_i, cb_i, n);
        gemm128v2_kernel<<<gemm_blocks, 256>>>(p_acc, Wlin_i, blin_i, p_acc, n, 1);
        bn_stats_kernel<<<512, 128>>>(n);
        bn_apply_kernel<<<elem_blocks, 256>>>(g_i, b_i,
            (layer == 0) ? p_x : (float*)d_out, n, (layer == 0) ? 1 : 0);
    }
}

// round 3
// speedup vs baseline: 1.5037x; 1.1125x over previous
#include <cuda_runtime.h>
#include <math.h>

#define NMAX 100000
#define HDIM 128
#define EMAX 625000
#define NEG_SLOPE 0.2f

// ---------------- scratch (device globals; no runtime allocation) -------------
__device__ float g_xs[NMAX * HDIM];     // source transform  x@Wl+bl
__device__ float g_xd[NMAX * HDIM];     // target transform  x@Wr+br
__device__ float g_acc[NMAX * HDIM];    // aggregated h -> residual gemm in place
__device__ float g_x[NMAX * HDIM];      // activations between layers
__device__ float g_sum[HDIM];
__device__ float g_sumsq[HDIM];

// CSR scratch
__device__ int g_deg[NMAX];
__device__ int g_fill[NMAX];
__device__ int g_rowptr[NMAX + 1];
__device__ int g_col[EMAX];
__device__ int g_blocksum[128];

// ---------------- f32x2 helpers -------------------------------------------------
__device__ __forceinline__ unsigned long long pack_dup(float a) {
    unsigned long long r;
    unsigned int u = __float_as_uint(a);
    asm("mov.b64 %0, {%1, %1};" : "=l"(r) : "r"(u));
    return r;
}
__device__ __forceinline__ void ffma2(unsigned long long& d, unsigned long long a,
                                      unsigned long long b) {
    asm("fma.rn.f32x2 %0, %1, %2, %0;" : "+l"(d) : "l"(a), "l"(b));
}
__device__ __forceinline__ void unpack2(unsigned long long v, float& lo, float& hi) {
    unsigned int a, b;
    asm("mov.b64 {%0, %1}, %2;" : "=r"(a), "=r"(b) : "l"(v));
    lo = __uint_as_float(a); hi = __uint_as_float(b);
}

// ---------------- CSR build ------------------------------------------------------
__global__ void csr_zero_kernel(int n) {
    int i = blockIdx.x * blockDim.x + threadIdx.x;
    if (i < n) { g_deg[i] = 0; g_fill[i] = 0; }
}
__global__ void csr_hist_kernel(const int* __restrict__ dst, int E) {
    int e = blockIdx.x * blockDim.x + threadIdx.x;
    if (e < E) atomicAdd(&g_deg[dst[e]], 1);
}
__global__ void csr_scanA_kernel(int n) {
    __shared__ int s[1024];
    int t = threadIdx.x;
    int i = blockIdx.x * 1024 + t;
    int v = (i < n) ? g_deg[i] : 0;
    s[t] = v;
    __syncthreads();
#pragma unroll
    for (int off = 1; off < 1024; off <<= 1) {
        int x = (t >= off) ? s[t - off] : 0;
        __syncthreads();
        s[t] += x;
        __syncthreads();
    }
    if (i < n) g_rowptr[i + 1] = s[t];
    if (t == 1023) g_blocksum[blockIdx.x] = s[t];
    if (i == 0) g_rowptr[0] = 0;
}
// fused block-prefix + add (replaces serial scanB + scanC)
__global__ void csr_scanC_kernel(int n) {
    __shared__ int s_off;
    int t = threadIdx.x;
    if (t < 32) {
        int b = blockIdx.x;
        int sum = 0;
        for (int i = t; i < b; i += 32) sum += g_blocksum[i];
#pragma unroll
        for (int o = 16; o; o >>= 1) sum += __shfl_xor_sync(0xffffffff, sum, o);
        if (t == 0) s_off = sum;
    }
    __syncthreads();
    int i = blockIdx.x * 1024 + t;
    if (i < n) g_rowptr[i + 1] += s_off;
}
__global__ void csr_fill_kernel(const int* __restrict__ src, const int* __restrict__ dst, int E) {
    int e = blockIdx.x * blockDim.x + threadIdx.x;
    if (e < E) {
        int d = dst[e];
        int pos = g_rowptr[d] + atomicAdd(&g_fill[d], 1);
        g_col[pos] = src[e];
    }
}

// ---------------- GEMM v2: Y = (residual? X : 0) + X @ W + bias ------------------
// 128x128 tile / block, 256 threads, 8x8 per thread, FFMA2 packed fp32.
// In-place (X==Y) safe: block reads only its own rows; writes after all reads.
// When residual != 0 also accumulates per-column sum / sumsq into g_sum / g_sumsq.
__global__ __launch_bounds__(256) void gemm128v2_kernel(
    const float* __restrict__ X, const float* __restrict__ W,
    const float* __restrict__ bias, float* __restrict__ Y, int n, int residual)
{
    __shared__ float sW[32][128];        // 16 KB per k-chunk (reused as stats scratch)
    __shared__ float sx[128][36];        // 18 KB (pad 4)

    const int tid = threadIdx.x;
    const int cg = tid & 15;             // column group: cols cg*8 .. cg*8+7
    const int rg = tid >> 4;             // row group:    rows rg*8 .. rg*8+7
    const int row0 = blockIdx.x * 128;

    unsigned long long acc[8][4];
#pragma unroll
    for (int r = 0; r < 8; r++)
#pragma unroll
        for (int c = 0; c < 4; c++) acc[r][c] = 0ull;

    for (int k0 = 0; k0 < 128; k0 += 32) {
#pragma unroll
        for (int i = 0; i < 4; i++) {
            int f = tid + i * 256;
            int r = f >> 5, c = (f & 31) * 4;
            *(float4*)&sW[r][c] = *(const float4*)&W[(k0 + r) * 128 + c];
        }
#pragma unroll
        for (int i = 0; i < 4; i++) {
            int f = tid + i * 256;
            int r = f >> 3, c = (f & 7) * 4;
            int gr = row0 + r;
            float4 v = make_float4(0.f, 0.f, 0.f, 0.f);
            if (gr < n) v = *(const float4*)&X[(size_t)gr * 128 + k0 + c];
            *(float4*)&sx[r][c] = v;
        }
        __syncthreads();

#pragma unroll 4
        for (int k = 0; k < 32; k++) {
            const unsigned long long* wp = (const unsigned long long*)&sW[k][cg * 8];
            unsigned long long w0 = wp[0], w1 = wp[1], w2 = wp[2], w3 = wp[3];
#pragma unroll
            for (int r = 0; r < 8; r++) {
                unsigned long long ad = pack_dup(sx[rg * 8 + r][k]);
                ffma2(acc[r][0], ad, w0);
                ffma2(acc[r][1], ad, w1);
                ffma2(acc[r][2], ad, w2);
                ffma2(acc[r][3], ad, w3);
            }
        }
        __syncthreads();
    }

    float4 b0 = *(const float4*)&bias[cg * 8];
    float4 b1 = *(const float4*)&bias[cg * 8 + 4];
    float cs[8], cq[8];
#pragma unroll
    for (int j = 0; j < 8; j++) { cs[j] = 0.f; cq[j] = 0.f; }

#pragma unroll
    for (int r = 0; r < 8; r++) {
        int gr = row0 + rg * 8 + r;
        if (gr >= n) continue;
        float o[8];
        unpack2(acc[r][0], o[0], o[1]);
        unpack2(acc[r][1], o[2], o[3]);
        unpack2(acc[r][2], o[4], o[5]);
        unpack2(acc[r][3], o[6], o[7]);
        o[0] += b0.x; o[1] += b0.y; o[2] += b0.z; o[3] += b0.w;
        o[4] += b1.x; o[5] += b1.y; o[6] += b1.z; o[7] += b1.w;
        if (residual) {
            float4 r0 = *(const float4*)&X[(size_t)gr * 128 + cg * 8];
            float4 r1 = *(const float4*)&X[(size_t)gr * 128 + cg * 8 + 4];
            o[0] += r0.x; o[1] += r0.y; o[2] += r0.z; o[3] += r0.w;
            o[4] += r1.x; o[5] += r1.y; o[6] += r1.z; o[7] += r1.w;
#pragma unroll
            for (int j = 0; j < 8; j++) { cs[j] += o[j]; cq[j] += o[j] * o[j]; }
        }
        float4 w0 = make_float4(o[0], o[1], o[2], o[3]);
        float4 w1 = make_float4(o[4], o[5], o[6], o[7]);
        *(float4*)&Y[(size_t)gr * 128 + cg * 8] = w0;
        *(float4*)&Y[(size_t)gr * 128 + cg * 8 + 4] = w1;
    }

    if (residual) {
        // reduce per-column stats across the 16 row-groups via sW scratch
        float (*red)[128] = (float (*)[128])sW;   // [32][128]: [0..15]=sum, [16..31]=sumsq
        __syncthreads();
#pragma unroll
        for (int j = 0; j < 8; j++) {
            red[rg][cg * 8 + j] = cs[j];
            red[16 + rg][cg * 8 + j] = cq[j];
        }
        __syncthreads();
        int col = tid & 127;
        int which = tid >> 7;            // 0 -> sum, 1 -> sumsq
        float t = 0.f;
#pragma unroll
        for (int r = 0; r < 16; r++) t += red[which * 16 + r][col];
        if (which == 0) atomicAdd(&g_sum[col], t);
        else            atomicAdd(&g_sumsq[col], t);
    }
}

// ---------------- aggregation: warp per node, exp without max-shift ---------------
// softmax(l) = exp(l)/sum(exp(l)) exactly; |logit| << 88 so no overflow.
__device__ __forceinline__ float dot_leaky(float4 xs4, float4 xd4, float4 at4) {
    float t, p = 0.0f;
    t = xs4.x + xd4.x; t = t > 0.f ? t : NEG_SLOPE * t; p = fmaf(t, at4.x, p);
    t = xs4.y + xd4.y; t = t > 0.f ? t : NEG_SLOPE * t; p = fmaf(t, at4.y, p);
    t = xs4.z + xd4.z; t = t > 0.f ? t : NEG_SLOPE * t; p = fmaf(t, at4.z, p);
    t = xs4.w + xd4.w; t = t > 0.f ? t : NEG_SLOPE * t; p = fmaf(t, at4.w, p);
    return p;
}

__global__ __launch_bounds__(256) void agg_kernel(
    const float* __restrict__ att, const float* __restrict__ cb, int n)
{
    // zero BN accumulators for this layer (consumed by the residual GEMM that follows)
    if (blockIdx.x == 0 && threadIdx.x < HDIM) {
        g_sum[threadIdx.x] = 0.0f;
        g_sumsq[threadIdx.x] = 0.0f;
    }
    int d = (blockIdx.x * blockDim.x + threadIdx.x) >> 5;
    int lane = threadIdx.x & 31;
    if (d >= n) return;

    float4 xd4 = *(const float4*)&g_xd[(size_t)d * 128 + lane * 4];
    float4 at4 = *(const float4*)&att[lane * 4];
    int e0 = g_rowptr[d], e1 = g_rowptr[d + 1];

    float den = 0.0f;
    float4 acc = make_float4(0.f, 0.f, 0.f, 0.f);

    int e = e0;
    for (; e + 2 <= e1; e += 2) {
        int s0 = g_col[e], s1 = g_col[e + 1];
        float4 a0 = *(const float4*)&g_xs[(size_t)s0 * 128 + lane * 4];
        float4 a1 = *(const float4*)&g_xs[(size_t)s1 * 128 + lane * 4];
        float p0 = dot_leaky(a0, xd4, at4);
        float p1 = dot_leaky(a1, xd4, at4);
#pragma unroll
        for (int o = 16; o; o >>= 1) {
            p0 += __shfl_xor_sync(0xffffffff, p0, o);
            p1 += __shfl_xor_sync(0xffffffff, p1, o);
        }
        float w0 = __expf(p0), w1 = __expf(p1);
        den += w0 + w1;
        acc.x = fmaf(w0, a0.x, fmaf(w1, a1.x, acc.x));
        acc.y = fmaf(w0, a0.y, fmaf(w1, a1.y, acc.y));
        acc.z = fmaf(w0, a0.z, fmaf(w1, a1.z, acc.z));
        acc.w = fmaf(w0, a0.w, fmaf(w1, a1.w, acc.w));
    }
    if (e < e1) {
        int s0 = g_col[e];
        float4 a0 = *(const float4*)&g_xs[(size_t)s0 * 128 + lane * 4];
        float p0 = dot_leaky(a0, xd4, at4);
#pragma unroll
        for (int o = 16; o; o >>= 1) p0 += __shfl_xor_sync(0xffffffff, p0, o);
        float w0 = __expf(p0);
        den += w0;
        acc.x = fmaf(w0, a0.x, acc.x);
        acc.y = fmaf(w0, a0.y, acc.y);
        acc.z = fmaf(w0, a0.z, acc.z);
        acc.w = fmaf(w0, a0.w, acc.w);
    }

    float inv = 1.0f / (den + 1e-16f);
    float4 cb4 = *(const float4*)&cb[lane * 4];
    float4 o;
    o.x = acc.x * inv + cb4.x;
    o.y = acc.y * inv + cb4.y;
    o.z = acc.z * inv + cb4.z;
    o.w = acc.w * inv + cb4.w;
    *(float4*)&g_acc[(size_t)d * 128 + lane * 4] = o;
}

// ---------------- BN apply (+ optional relu) ---------------------------------------
__global__ __launch_bounds__(256) void bn_apply_kernel(
    const float* __restrict__ gamma, const float* __restrict__ beta,
    float* __restrict__ out, int n, int do_relu)
{
    int i = blockIdx.x * blockDim.x + threadIdx.x;
    if (i >= n * HDIM) return;
    int h = i & 127;
    float inv_n = 1.0f / (float)n;
    float mu = g_sum[h] * inv_n;
    float var = g_sumsq[h] * inv_n - mu * mu;
    float v = (g_acc[i] - mu) * rsqrtf(var + 1e-5f) * gamma[h] + beta[h];
    if (do_relu) v = fmaxf(v, 0.0f);
    out[i] = v;
}

// ---------------- host driver -------------------------------------------------------
extern "C" void kernel_launch(void* const* d_in, const int* in_sizes, int n_in,
                              void* d_out, int out_size)
{
    const float* x     = (const float*)d_in[0];
    const int*   ei    = (const int*)  d_in[1];
    const float* Wl    = (const float*)d_in[2];
    const float* bl    = (const float*)d_in[3];
    const float* Wr    = (const float*)d_in[4];
    const float* br    = (const float*)d_in[5];
    const float* att   = (const float*)d_in[6];
    const float* cb    = (const float*)d_in[7];
    const float* Wlin  = (const float*)d_in[8];
    const float* blin  = (const float*)d_in[9];
    const float* gamma = (const float*)d_in[10];
    const float* beta  = (const float*)d_in[11];

    const int n = in_sizes[0] / HDIM;
    const int E = in_sizes[1] / 2;
    const int* src = ei;
    const int* dst = ei + E;

    void* p;
    cudaGetSymbolAddress(&p, g_xs);  float* p_xs  = (float*)p;
    cudaGetSymbolAddress(&p, g_xd);  float* p_xd  = (float*)p;
    cudaGetSymbolAddress(&p, g_acc); float* p_acc = (float*)p;
    cudaGetSymbolAddress(&p, g_x);   float* p_x   = (float*)p;

    const int elem_blocks = (n * HDIM + 255) / 256;
    const int gemm_blocks = (n + 127) / 128;
    const int agg_blocks  = (n + 7) / 8;
    const int e_blocks    = (E + 255) / 256;
    const int scan_blocks = (n + 1023) / 1024;

    // CSR build interleaved with layer-0 GEMMs (gemm placed 4th for ncu capture)
    csr_zero_kernel<<<(n + 255) / 256, 256>>>(n);                               // 1
    csr_hist_kernel<<<e_blocks, 256>>>(dst, E);                                 // 2
    csr_scanA_kernel<<<scan_blocks, 1024>>>(n);                                 // 3
    gemm128v2_kernel<<<gemm_blocks, 256>>>(x, Wl, bl, p_xs, n, 0);              // 4 (profiled)
    csr_scanC_kernel<<<scan_blocks, 1024>>>(n);                                 // 5
    csr_fill_kernel<<<e_blocks, 256>>>(src, dst, E);                            // 6
    gemm128v2_kernel<<<gemm_blocks, 256>>>(x, Wr, br, p_xd, n, 0);              // 7

    for (int layer = 0; layer < 2; layer++) {
        const float* xin = (layer == 0) ? x : p_x;
        const float* att_i  = att  + layer * HDIM;
        const float* cb_i   = cb   + layer * HDIM;
        const float* Wlin_i = Wlin + (size_t)layer * HDIM * HDIM;
        const float* blin_i = blin + layer * HDIM;
        const float* g_i    = gamma + layer * HDIM;
        const float* b_i    = beta  + layer * HDIM;

        if (layer == 1) {
            gemm128v2_kernel<<<gemm_blocks, 256>>>(xin, Wl + HDIM * HDIM, bl + HDIM, p_xs, n, 0);
            gemm128v2_kernel<<<gemm_blocks, 256>>>(xin, Wr + HDIM * HDIM, br + HDIM, p_xd, n, 0);
        }
        agg_kernel<<<agg_blocks, 256>>>(att_i, cb_i, n);
        gemm128v2_kernel<<<gemm_blocks, 256>>>(p_acc, Wlin_i, blin_i, p_acc, n, 1);
        bn_apply_kernel<<<elem_blocks, 256>>>(g_i, b_i,
            (layer == 0) ? p_x : (float*)d_out, n, (layer == 0) ? 1 : 0);
    }
}

// round 4
// speedup vs baseline: 1.7628x; 1.1723x over previous
#include <cuda_runtime.h>
#include <math.h>

#define NMAX 100000
#define HDIM 128
#define EMAX 625000
#define NEG_SLOPE 0.2f

// ---------------- scratch (device globals; no runtime allocation) -------------
__device__ float g_xs[NMAX * HDIM];     // source transform  x@Wl+bl
__device__ float g_xd[NMAX * HDIM];     // target transform  x@Wr+br
__device__ float g_acc[NMAX * HDIM];    // aggregated h -> residual gemm in place
__device__ float g_sum[HDIM];
__device__ float g_sumsq[HDIM];

// CSR scratch
__device__ int g_deg[NMAX];
__device__ int g_fill[NMAX];
__device__ int g_rowptr[NMAX + 1];
__device__ int g_col[EMAX];
__device__ int g_blocksum[128];

// ---------------- f32x2 helpers -------------------------------------------------
__device__ __forceinline__ unsigned long long pack_dup(float a) {
    unsigned long long r;
    unsigned int u = __float_as_uint(a);
    asm("mov.b64 %0, {%1, %1};" : "=l"(r) : "r"(u));
    return r;
}
__device__ __forceinline__ unsigned long long pack2f(float a, float b) {
    unsigned long long r;
    asm("mov.b64 %0, {%1, %2};" : "=l"(r) : "r"(__float_as_uint(a)), "r"(__float_as_uint(b)));
    return r;
}
__device__ __forceinline__ void ffma2(unsigned long long& d, unsigned long long a,
                                      unsigned long long b) {
    asm("fma.rn.f32x2 %0, %1, %2, %0;" : "+l"(d) : "l"(a), "l"(b));
}
__device__ __forceinline__ void unpack2(unsigned long long v, float& lo, float& hi) {
    unsigned int a, b;
    asm("mov.b64 {%0, %1}, %2;" : "=r"(a), "=r"(b) : "l"(v));
    lo = __uint_as_float(a); hi = __uint_as_float(b);
}

// ---------------- CSR build ------------------------------------------------------
__global__ void csr_zero_kernel(int n) {
    int i = blockIdx.x * blockDim.x + threadIdx.x;
    if (i < n) { g_deg[i] = 0; g_fill[i] = 0; }
}
__global__ void csr_hist_kernel(const int* __restrict__ dst, int E) {
    int e = blockIdx.x * blockDim.x + threadIdx.x;
    if (e < E) atomicAdd(&g_deg[dst[e]], 1);
}
__global__ void csr_scanA_kernel(int n) {
    __shared__ int s[1024];
    int t = threadIdx.x;
    int i = blockIdx.x * 1024 + t;
    int v = (i < n) ? g_deg[i] : 0;
    s[t] = v;
    __syncthreads();
#pragma unroll
    for (int off = 1; off < 1024; off <<= 1) {
        int x = (t >= off) ? s[t - off] : 0;
        __syncthreads();
        s[t] += x;
        __syncthreads();
    }
    if (i < n) g_rowptr[i + 1] = s[t];
    if (t == 1023) g_blocksum[blockIdx.x] = s[t];
    if (i == 0) g_rowptr[0] = 0;
}
__global__ void csr_scanC_kernel(int n) {
    __shared__ int s_off;
    int t = threadIdx.x;
    if (t < 32) {
        int b = blockIdx.x;
        int sum = 0;
        for (int i = t; i < b; i += 32) sum += g_blocksum[i];
#pragma unroll
        for (int o = 16; o; o >>= 1) sum += __shfl_xor_sync(0xffffffff, sum, o);
        if (t == 0) s_off = sum;
    }
    __syncthreads();
    int i = blockIdx.x * 1024 + t;
    if (i < n) g_rowptr[i + 1] += s_off;
}
__global__ void csr_fill_kernel(const int* __restrict__ src, const int* __restrict__ dst, int E) {
    int e = blockIdx.x * blockDim.x + threadIdx.x;
    if (e < E) {
        int d = dst[e];
        int pos = g_rowptr[d] + atomicAdd(&g_fill[d], 1);
        g_col[pos] = src[e];
    }
}

// ---------------- GEMM v3 ---------------------------------------------------------
// mode 0: Y = X@W + b
// mode 1: Y = X + X@W + b  (in place, X==Y) + column stats into g_sum/g_sumsq
// mode 2: Y = f(X)@W + b   where f = BN(g_sum,g_sumsq,gamma,beta) + relu (per column)
// 128x128 tile / block, 256 threads, 8x8 per thread, FFMA2; 2 CTAs/SM.
__global__ __launch_bounds__(256, 2) void gemm128v3_kernel(
    const float* __restrict__ X, const float* __restrict__ W,
    const float* __restrict__ bias, float* __restrict__ Y, int n,
    int mode, const float* __restrict__ bng, const float* __restrict__ bnb)
{
    __shared__ unsigned long long sW2[4][16][16];   // 8 KB  [colpair j][k][cg]
    __shared__ unsigned long long sx2[128][17];     // 17 KB [row][k], dup-packed
    __shared__ float s_scale[128];
    __shared__ float s_shift[128];

    const int tid = threadIdx.x;
    const int cg = tid & 15;             // column group: cols cg*8 .. cg*8+7
    const int rg = tid >> 4;             // row group:    rows rg*8 .. rg*8+7
    const int row0 = blockIdx.x * 128;

    if (mode == 2) {
        if (tid < 128) {
            float inv_n = 1.0f / (float)n;
            float mu = g_sum[tid] * inv_n;
            float var = g_sumsq[tid] * inv_n - mu * mu;
            float sc = bng[tid] * rsqrtf(var + 1e-5f);
            s_scale[tid] = sc;
            s_shift[tid] = bnb[tid] - mu * sc;
        }
        __syncthreads();
    }

    unsigned long long acc[8][4];
#pragma unroll
    for (int r = 0; r < 8; r++)
#pragma unroll
        for (int c = 0; c < 4; c++) acc[r][c] = 0ull;

    for (int k0 = 0; k0 < 128; k0 += 16) {
        // stage W chunk [16][128] -> sW2[j][k][cg]
#pragma unroll
        for (int i = 0; i < 2; i++) {
            int f = tid + i * 256;
            int r = f >> 5, c = (f & 31) * 4;
            float4 v = *(const float4*)&W[(k0 + r) * 128 + c];
            int j0 = (c & 7) >> 1;       // 0 or 2
            int cgi = c >> 3;
            sW2[j0][r][cgi]     = pack2f(v.x, v.y);
            sW2[j0 + 1][r][cgi] = pack2f(v.z, v.w);
        }
        // stage X chunk [128][16] dup-packed
#pragma unroll
        for (int i = 0; i < 2; i++) {
            int f = tid + i * 256;
            int r = f >> 2, c = (f & 3) * 4;
            int gr = row0 + r;
            float4 v = make_float4(0.f, 0.f, 0.f, 0.f);
            if (gr < n) v = *(const float4*)&X[(size_t)gr * 128 + k0 + c];
            if (mode == 2) {
                int cc = k0 + c;
                v.x = fmaxf(0.f, fmaf(v.x, s_scale[cc],     s_shift[cc]));
                v.y = fmaxf(0.f, fmaf(v.y, s_scale[cc + 1], s_shift[cc + 1]));
                v.z = fmaxf(0.f, fmaf(v.z, s_scale[cc + 2], s_shift[cc + 2]));
                v.w = fmaxf(0.f, fmaf(v.w, s_scale[cc + 3], s_shift[cc + 3]));
            }
            sx2[r][c + 0] = pack_dup(v.x);
            sx2[r][c + 1] = pack_dup(v.y);
            sx2[r][c + 2] = pack_dup(v.z);
            sx2[r][c + 3] = pack_dup(v.w);
        }
        __syncthreads();

#pragma unroll
        for (int k = 0; k < 16; k++) {
            unsigned long long w0 = sW2[0][k][cg];
            unsigned long long w1 = sW2[1][k][cg];
            unsigned long long w2 = sW2[2][k][cg];
            unsigned long long w3 = sW2[3][k][cg];
#pragma unroll
            for (int r = 0; r < 8; r++) {
                unsigned long long ad = sx2[rg * 8 + r][k];
                ffma2(acc[r][0], ad, w0);
                ffma2(acc[r][1], ad, w1);
                ffma2(acc[r][2], ad, w2);
                ffma2(acc[r][3], ad, w3);
            }
        }
        __syncthreads();
    }

    float4 b0 = *(const float4*)&bias[cg * 8];
    float4 b1 = *(const float4*)&bias[cg * 8 + 4];
    float cs[8], cq[8];
#pragma unroll
    for (int j = 0; j < 8; j++) { cs[j] = 0.f; cq[j] = 0.f; }

#pragma unroll
    for (int r = 0; r < 8; r++) {
        int gr = row0 + rg * 8 + r;
        if (gr >= n) continue;
        float o[8];
        unpack2(acc[r][0], o[0], o[1]);
        unpack2(acc[r][1], o[2], o[3]);
        unpack2(acc[r][2], o[4], o[5]);
        unpack2(acc[r][3], o[6], o[7]);
        o[0] += b0.x; o[1] += b0.y; o[2] += b0.z; o[3] += b0.w;
        o[4] += b1.x; o[5] += b1.y; o[6] += b1.z; o[7] += b1.w;
        if (mode == 1) {
            float4 r0 = *(const float4*)&X[(size_t)gr * 128 + cg * 8];
            float4 r1 = *(const float4*)&X[(size_t)gr * 128 + cg * 8 + 4];
            o[0] += r0.x; o[1] += r0.y; o[2] += r0.z; o[3] += r0.w;
            o[4] += r1.x; o[5] += r1.y; o[6] += r1.z; o[7] += r1.w;
#pragma unroll
            for (int j = 0; j < 8; j++) { cs[j] += o[j]; cq[j] += o[j] * o[j]; }
        }
        *(float4*)&Y[(size_t)gr * 128 + cg * 8]     = make_float4(o[0], o[1], o[2], o[3]);
        *(float4*)&Y[(size_t)gr * 128 + cg * 8 + 4] = make_float4(o[4], o[5], o[6], o[7]);
    }

    if (mode == 1) {
        // reduce per-column stats across the 16 row-groups via sx2 scratch
        float (*red)[128] = (float (*)[128])sx2;   // [32][128]
        __syncthreads();
#pragma unroll
        for (int j = 0; j < 8; j++) {
            red[rg][cg * 8 + j] = cs[j];
            red[16 + rg][cg * 8 + j] = cq[j];
        }
        __syncthreads();
        int col = tid & 127;
        int which = tid >> 7;
        float t = 0.f;
#pragma unroll
        for (int r = 0; r < 16; r++) t += red[which * 16 + r][col];
        if (which == 0) atomicAdd(&g_sum[col], t);
        else            atomicAdd(&g_sumsq[col], t);
    }
}

// ---------------- aggregation: warp per node, exp without max-shift ---------------
__device__ __forceinline__ float dot_leaky(float4 xs4, float4 xd4, float4 at4) {
    float t, p = 0.0f;
    t = xs4.x + xd4.x; t = t > 0.f ? t : NEG_SLOPE * t; p = fmaf(t, at4.x, p);
    t = xs4.y + xd4.y; t = t > 0.f ? t : NEG_SLOPE * t; p = fmaf(t, at4.y, p);
    t = xs4.z + xd4.z; t = t > 0.f ? t : NEG_SLOPE * t; p = fmaf(t, at4.z, p);
    t = xs4.w + xd4.w; t = t > 0.f ? t : NEG_SLOPE * t; p = fmaf(t, at4.w, p);
    return p;
}

__global__ __launch_bounds__(256) void agg_kernel(
    const float* __restrict__ att, const float* __restrict__ cb, int n)
{
    if (blockIdx.x == 0 && threadIdx.x < HDIM) {
        g_sum[threadIdx.x] = 0.0f;
        g_sumsq[threadIdx.x] = 0.0f;
    }
    int d = (blockIdx.x * blockDim.x + threadIdx.x) >> 5;
    int lane = threadIdx.x & 31;
    if (d >= n) return;

    float4 xd4 = *(const float4*)&g_xd[(size_t)d * 128 + lane * 4];
    float4 at4 = *(const float4*)&att[lane * 4];
    int e0 = g_rowptr[d], e1 = g_rowptr[d + 1];

    float den = 0.0f;
    float4 acc = make_float4(0.f, 0.f, 0.f, 0.f);

    int e = e0;
    for (; e + 2 <= e1; e += 2) {
        int s0 = g_col[e], s1 = g_col[e + 1];
        float4 a0 = *(const float4*)&g_xs[(size_t)s0 * 128 + lane * 4];
        float4 a1 = *(const float4*)&g_xs[(size_t)s1 * 128 + lane * 4];
        float p0 = dot_leaky(a0, xd4, at4);
        float p1 = dot_leaky(a1, xd4, at4);
#pragma unroll
        for (int o = 16; o; o >>= 1) {
            p0 += __shfl_xor_sync(0xffffffff, p0, o);
            p1 += __shfl_xor_sync(0xffffffff, p1, o);
        }
        float w0 = __expf(p0), w1 = __expf(p1);
        den += w0 + w1;
        acc.x = fmaf(w0, a0.x, fmaf(w1, a1.x, acc.x));
        acc.y = fmaf(w0, a0.y, fmaf(w1, a1.y, acc.y));
        acc.z = fmaf(w0, a0.z, fmaf(w1, a1.z, acc.z));
        acc.w = fmaf(w0, a0.w, fmaf(w1, a1.w, acc.w));
    }
    if (e < e1) {
        int s0 = g_col[e];
        float4 a0 = *(const float4*)&g_xs[(size_t)s0 * 128 + lane * 4];
        float p0 = dot_leaky(a0, xd4, at4);
#pragma unroll
        for (int o = 16; o; o >>= 1) p0 += __shfl_xor_sync(0xffffffff, p0, o);
        float w0 = __expf(p0);
        den += w0;
        acc.x = fmaf(w0, a0.x, acc.x);
        acc.y = fmaf(w0, a0.y, acc.y);
        acc.z = fmaf(w0, a0.z, acc.z);
        acc.w = fmaf(w0, a0.w, acc.w);
    }

    float inv = 1.0f / (den + 1e-16f);
    float4 cb4 = *(const float4*)&cb[lane * 4];
    float4 o;
    o.x = acc.x * inv + cb4.x;
    o.y = acc.y * inv + cb4.y;
    o.z = acc.z * inv + cb4.z;
    o.w = acc.w * inv + cb4.w;
    *(float4*)&g_acc[(size_t)d * 128 + lane * 4] = o;
}

// ---------------- BN apply (final layer output) -------------------------------------
__global__ __launch_bounds__(256) void bn_apply_kernel(
    const float* __restrict__ gamma, const float* __restrict__ beta,
    float* __restrict__ out, int n)
{
    int i = blockIdx.x * blockDim.x + threadIdx.x;
    if (i >= n * HDIM) return;
    int h = i & 127;
    float inv_n = 1.0f / (float)n;
    float mu = g_sum[h] * inv_n;
    float var = g_sumsq[h] * inv_n - mu * mu;
    out[i] = (g_acc[i] - mu) * rsqrtf(var + 1e-5f) * gamma[h] + beta[h];
}

// ---------------- host driver -------------------------------------------------------
extern "C" void kernel_launch(void* const* d_in, const int* in_sizes, int n_in,
                              void* d_out, int out_size)
{
    const float* x     = (const float*)d_in[0];
    const int*   ei    = (const int*)  d_in[1];
    const float* Wl    = (const float*)d_in[2];
    const float* bl    = (const float*)d_in[3];
    const float* Wr    = (const float*)d_in[4];
    const float* br    = (const float*)d_in[5];
    const float* att   = (const float*)d_in[6];
    const float* cb    = (const float*)d_in[7];
    const float* Wlin  = (const float*)d_in[8];
    const float* blin  = (const float*)d_in[9];
    const float* gamma = (const float*)d_in[10];
    const float* beta  = (const float*)d_in[11];

    const int n = in_sizes[0] / HDIM;
    const int E = in_sizes[1] / 2;
    const int* src = ei;
    const int* dst = ei + E;

    void* p;
    cudaGetSymbolAddress(&p, g_xs);  float* p_xs  = (float*)p;
    cudaGetSymbolAddress(&p, g_xd);  float* p_xd  = (float*)p;
    cudaGetSymbolAddress(&p, g_acc); float* p_acc = (float*)p;

    const int elem_blocks = (n * HDIM + 255) / 256;
    const int gemm_blocks = (n + 127) / 128;
    const int agg_blocks  = (n + 7) / 8;
    const int e_blocks    = (E + 255) / 256;
    const int scan_blocks = (n + 1023) / 1024;

    csr_zero_kernel<<<(n + 255) / 256, 256>>>(n);
    csr_hist_kernel<<<e_blocks, 256>>>(dst, E);
    csr_scanA_kernel<<<scan_blocks, 1024>>>(n);
    gemm128v3_kernel<<<gemm_blocks, 256>>>(x, Wl, bl, p_xs, n, 0, nullptr, nullptr); // profiled
    csr_scanC_kernel<<<scan_blocks, 1024>>>(n);
    csr_fill_kernel<<<e_blocks, 256>>>(src, dst, E);
    gemm128v3_kernel<<<gemm_blocks, 256>>>(x, Wr, br, p_xd, n, 0, nullptr, nullptr);

    // layer 0
    agg_kernel<<<agg_blocks, 256>>>(att, cb, n);
    gemm128v3_kernel<<<gemm_blocks, 256>>>(p_acc, Wlin, blin, p_acc, n, 1, nullptr, nullptr);

    // layer 1: BN(layer0)+relu fused into the x-load of both transform GEMMs
    gemm128v3_kernel<<<gemm_blocks, 256>>>(p_acc, Wl + HDIM * HDIM, bl + HDIM, p_xs, n, 2, gamma, beta);
    gemm128v3_kernel<<<gemm_blocks, 256>>>(p_acc, Wr + HDIM * HDIM, br + HDIM, p_xd, n, 2, gamma, beta);
    agg_kernel<<<agg_blocks, 256>>>(att + HDIM, cb + HDIM, n);
    gemm128v3_kernel<<<gemm_blocks, 256>>>(p_acc, Wlin + HDIM * HDIM, blin + HDIM, p_acc, n, 1, nullptr, nullptr);
    bn_apply_kernel<<<elem_blocks, 256>>>(gamma + HDIM, beta + HDIM, (float*)d_out, n);
}

// round 7
// speedup vs baseline: 1.9134x; 1.0855x over previous
#include <cuda_runtime.h>
#include <cuda_bf16.h>
#include <math.h>
#include <stdint.h>

#define NMAX 100000
#define HDIM 128
#define EMAX 625000
#define NEG_SLOPE 0.2f
#define KPAD 136                 // W image row stride (bf16 elems), 272B
#define APADB 80                 // A smem row stride bytes (40 bf16)

// ---------------- scratch ---------------------------------------------------------
__device__ float g_xs[NMAX * HDIM];
__device__ float g_xd[NMAX * HDIM];
__device__ float g_acc[NMAX * HDIM];
__device__ float g_h[NMAX * HDIM];
__device__ float g_sum[HDIM];
__device__ float g_sumsq[HDIM];
__device__ __align__(16) __nv_bfloat16 g_Wbf[6 * 2 * 128 * KPAD];  // [mat][hi/lo][n][k]

// CSR scratch
__device__ int g_deg[NMAX];
__device__ int g_fill[NMAX];
__device__ int g_rowptr[NMAX + 1];
__device__ int g_col[EMAX];
__device__ int g_blocksum[128];

// ---------------- helpers ----------------------------------------------------------
__device__ __forceinline__ uint32_t smem_to_u32(const void* p) {
    uint32_t a;
    asm("{ .reg .u64 t; cvta.to.shared.u64 t, %1; cvt.u32.u64 %0, t; }" : "=r"(a) : "l"(p));
    return a;
}
__device__ __forceinline__ void ldsm_x4(uint32_t& r0, uint32_t& r1, uint32_t& r2,
                                        uint32_t& r3, uint32_t addr) {
    asm volatile("ldmatrix.sync.aligned.m8n8.x4.shared.b16 {%0,%1,%2,%3}, [%4];"
                 : "=r"(r0), "=r"(r1), "=r"(r2), "=r"(r3) : "r"(addr));
}
__device__ __forceinline__ void mma_bf16(float* c, const uint32_t* a, const uint32_t* b) {
    asm volatile(
        "mma.sync.aligned.m16n8k16.row.col.f32.bf16.bf16.f32 "
        "{%0,%1,%2,%3}, {%4,%5,%6,%7}, {%8,%9}, {%0,%1,%2,%3};"
        : "+f"(c[0]), "+f"(c[1]), "+f"(c[2]), "+f"(c[3])
        : "r"(a[0]), "r"(a[1]), "r"(a[2]), "r"(a[3]), "r"(b[0]), "r"(b[1]));
}
__device__ __forceinline__ uint32_t pack_hi(float x, float y) {
    __nv_bfloat16 h0 = __float2bfloat16(x), h1 = __float2bfloat16(y);
    return (uint32_t)__bfloat16_as_ushort(h0) | ((uint32_t)__bfloat16_as_ushort(h1) << 16);
}
__device__ __forceinline__ uint32_t pack_lo(float x, float y) {
    __nv_bfloat16 h0 = __float2bfloat16(x), h1 = __float2bfloat16(y);
    __nv_bfloat16 l0 = __float2bfloat16(x - __bfloat162float(h0));
    __nv_bfloat16 l1 = __float2bfloat16(y - __bfloat162float(h1));
    return (uint32_t)__bfloat16_as_ushort(l0) | ((uint32_t)__bfloat16_as_ushort(l1) << 16);
}

// ---------------- prep: transpose + hi/lo split W ------------------------------------
__global__ void prep_w_kernel(const float* __restrict__ Wl, const float* __restrict__ Wr,
                              const float* __restrict__ Wlin) {
    int idx = blockIdx.x * blockDim.x + threadIdx.x;
    if (idx >= 6 * 128 * 128) return;
    int m = idx >> 14;
    int r = idx & 16383;
    int nrow = r >> 7;
    int k = r & 127;
    int layer = m / 3, which = m % 3;
    const float* W = (which == 0 ? Wl : which == 1 ? Wr : Wlin) + (size_t)layer * HDIM * HDIM;
    float w = W[k * 128 + nrow];
    __nv_bfloat16 h = __float2bfloat16(w);
    __nv_bfloat16 l = __float2bfloat16(w - __bfloat162float(h));
    g_Wbf[((size_t)(m * 2 + 0) * 128 + nrow) * KPAD + k] = h;
    g_Wbf[((size_t)(m * 2 + 1) * 128 + nrow) * KPAD + k] = l;
}

// ---------------- GEMM (mma.sync bf16 split): Y = op(X) @ W + bias -------------------
// mode 0: plain    mode 1: Y = X + X@W + b (X != Y)    mode 2: X := BN+relu(X) first
// CTA tile 128 rows x 64 cols (blockIdx.y = col half). 256 threads, warps 4x2.
#define SM_AH 0
#define SM_AL 10240
#define SM_BH 20480
#define SM_BL 37888
#define SM_TOTAL 55296

__global__ __launch_bounds__(256) void gemm_mma_kernel(
    const float* __restrict__ X, int wimg, const float* __restrict__ bias,
    float* __restrict__ Y, int n, int mode,
    const float* __restrict__ bng, const float* __restrict__ bnb)
{
    extern __shared__ char smem[];
    __shared__ float s_scale[128];
    __shared__ float s_shift[128];
    const uint32_t sb = smem_to_u32(smem);
    const int tid = threadIdx.x;
    const int wid = tid >> 5;
    const int lane = tid & 31;
    const int row0 = blockIdx.x * 128;
    const int col0 = blockIdx.y * 64;
    const int warp_m = wid & 3;      // 4 x 32 rows
    const int warp_n = wid >> 2;     // 2 x 32 cols

    if (mode == 2 && tid < 128) {
        float inv_n = 1.0f / (float)n;
        float mu = g_sum[tid] * inv_n;
        float var = g_sumsq[tid] * inv_n - mu * mu;
        float sc = bng[tid] * rsqrtf(var + 1e-5f);
        s_scale[tid] = sc;
        s_shift[tid] = bnb[tid] - mu * sc;
    }

    // stage W half-tile [64][KPAD] hi+lo (pre-transposed, padded; layout-identical copy)
    {
        const uint4* gBh = (const uint4*)(g_Wbf + ((size_t)(wimg * 2 + 0) * 128 + col0) * KPAD);
        const uint4* gBl = (const uint4*)(g_Wbf + ((size_t)(wimg * 2 + 1) * 128 + col0) * KPAD);
        uint4* sh = (uint4*)(smem + SM_BH);
        uint4* sl = (uint4*)(smem + SM_BL);
        for (int i = tid; i < 64 * KPAD * 2 / 16; i += 256) {   // 1088 uint4
            sh[i] = gBh[i];
            sl[i] = gBl[i];
        }
    }
    // order s_scale/s_shift writes (and W staging) before ANY thread reads them below.
    // (this sync was missing: kc==0 A-staging read s_scale unsynchronized -> race)
    __syncthreads();

    float acc[2][4][4];
#pragma unroll
    for (int a = 0; a < 2; a++)
#pragma unroll
        for (int b = 0; b < 4; b++)
#pragma unroll
            for (int c = 0; c < 4; c++) acc[a][b][c] = 0.0f;

    // per-lane ldmatrix base addresses
    const uint32_t aAh = sb + SM_AH + (warp_m * 32 + (lane & 15)) * APADB + ((lane >> 4) * 8) * 2;
    const uint32_t aAl = aAh + (SM_AL - SM_AH);
    const uint32_t aBh = sb + SM_BH + (warp_n * 32 + (lane & 7) + (lane >> 4) * 8) * (KPAD * 2)
                       + (((lane >> 3) & 1) * 8) * 2;
    const uint32_t aBl = aBh + (SM_BL - SM_BH);

    for (int kc = 0; kc < 128; kc += 32) {
        // stage A chunk [128 rows][32 k] hi+lo, padded stride
        if (kc) __syncthreads();   // protect smem reuse from previous iter's ldmatrix
#pragma unroll
        for (int i = tid; i < 1024; i += 256) {
            int row = i >> 3;
            int c4 = (i & 7) * 4;
            int gr = row0 + row;
            float4 v = make_float4(0.f, 0.f, 0.f, 0.f);
            if (gr < n) v = *(const float4*)&X[(size_t)gr * 128 + kc + c4];
            if (mode == 2) {
                int cc = kc + c4;
                v.x = fmaxf(0.f, fmaf(v.x, s_scale[cc],     s_shift[cc]));
                v.y = fmaxf(0.f, fmaf(v.y, s_scale[cc + 1], s_shift[cc + 1]));
                v.z = fmaxf(0.f, fmaf(v.z, s_scale[cc + 2], s_shift[cc + 2]));
                v.w = fmaxf(0.f, fmaf(v.w, s_scale[cc + 3], s_shift[cc + 3]));
            }
            *(uint2*)(smem + SM_AH + row * APADB + c4 * 2) =
                make_uint2(pack_hi(v.x, v.y), pack_hi(v.z, v.w));
            *(uint2*)(smem + SM_AL + row * APADB + c4 * 2) =
                make_uint2(pack_lo(v.x, v.y), pack_lo(v.z, v.w));
        }
        __syncthreads();

#pragma unroll
        for (int kk = 0; kk < 32; kk += 16) {
            uint32_t ah[2][4], al[2][4];
#pragma unroll
            for (int ms = 0; ms < 2; ms++) {
                uint32_t off = ms * 16 * APADB + kk * 2;
                ldsm_x4(ah[ms][0], ah[ms][1], ah[ms][2], ah[ms][3], aAh + off);
                ldsm_x4(al[ms][0], al[ms][1], al[ms][2], al[ms][3], aAl + off);
            }
            uint32_t bh[4][2], bl[4][2];
#pragma unroll
            for (int nn = 0; nn < 2; nn++) {
                uint32_t off = nn * 16 * (KPAD * 2) + (kc + kk) * 2;
                uint32_t t0, t1, t2, t3;
                ldsm_x4(t0, t1, t2, t3, aBh + off);
                bh[nn * 2][0] = t0; bh[nn * 2][1] = t1;
                bh[nn * 2 + 1][0] = t2; bh[nn * 2 + 1][1] = t3;
                ldsm_x4(t0, t1, t2, t3, aBl + off);
                bl[nn * 2][0] = t0; bl[nn * 2][1] = t1;
                bl[nn * 2 + 1][0] = t2; bl[nn * 2 + 1][1] = t3;
            }
#pragma unroll
            for (int ms = 0; ms < 2; ms++)
#pragma unroll
                for (int ns = 0; ns < 4; ns++) {
                    mma_bf16(acc[ms][ns], ah[ms], bh[ns]);   // hi*hi
                    mma_bf16(acc[ms][ns], al[ms], bh[ns]);   // lo*hi
                    mma_bf16(acc[ms][ns], ah[ms], bl[ns]);   // hi*lo
                }
        }
    }

    // epilogue
    const int er = row0 + warp_m * 32 + (lane >> 2);
    const int ec = col0 + warp_n * 32 + (lane & 3) * 2;
#pragma unroll
    for (int ms = 0; ms < 2; ms++) {
#pragma unroll
        for (int ns = 0; ns < 4; ns++) {
            int r = er + ms * 16;
            int c = ec + ns * 8;
            float b0 = __ldg(&bias[c]), b1 = __ldg(&bias[c + 1]);
            if (r < n) {
                float2 o = make_float2(acc[ms][ns][0] + b0, acc[ms][ns][1] + b1);
                if (mode == 1) {
                    const float2 rv = *(const float2*)&X[(size_t)r * 128 + c];
                    o.x += rv.x; o.y += rv.y;
                }
                *(float2*)&Y[(size_t)r * 128 + c] = o;
            }
            if (r + 8 < n) {
                float2 o = make_float2(acc[ms][ns][2] + b0, acc[ms][ns][3] + b1);
                if (mode == 1) {
                    const float2 rv = *(const float2*)&X[(size_t)(r + 8) * 128 + c];
                    o.x += rv.x; o.y += rv.y;
                }
                *(float2*)&Y[(size_t)(r + 8) * 128 + c] = o;
            }
        }
    }
}

// ---------------- CSR build ------------------------------------------------------
__global__ void csr_zero_kernel(int n) {
    int i = blockIdx.x * blockDim.x + threadIdx.x;
    if (i < n) { g_deg[i] = 0; g_fill[i] = 0; }
}
__global__ void csr_hist_kernel(const int* __restrict__ dst, int E) {
    int e = blockIdx.x * blockDim.x + threadIdx.x;
    if (e < E) atomicAdd(&g_deg[dst[e]], 1);
}
__global__ void csr_scanA_kernel(int n) {
    __shared__ int s[1024];
    int t = threadIdx.x;
    int i = blockIdx.x * 1024 + t;
    int v = (i < n) ? g_deg[i] : 0;
    s[t] = v;
    __syncthreads();
#pragma unroll
    for (int off = 1; off < 1024; off <<= 1) {
        int x = (t >= off) ? s[t - off] : 0;
        __syncthreads();
        s[t] += x;
        __syncthreads();
    }
    if (i < n) g_rowptr[i + 1] = s[t];
    if (t == 1023) g_blocksum[blockIdx.x] = s[t];
    if (i == 0) g_rowptr[0] = 0;
}
__global__ void csr_scanC_kernel(int n) {
    __shared__ int s_off;
    int t = threadIdx.x;
    if (t < 32) {
        int b = blockIdx.x;
        int sum = 0;
        for (int i = t; i < b; i += 32) sum += g_blocksum[i];
#pragma unroll
        for (int o = 16; o; o >>= 1) sum += __shfl_xor_sync(0xffffffff, sum, o);
        if (t == 0) s_off = sum;
    }
    __syncthreads();
    int i = blockIdx.x * 1024 + t;
    if (i < n) g_rowptr[i + 1] += s_off;
}
__global__ void csr_fill_kernel(const int* __restrict__ src, const int* __restrict__ dst, int E) {
    int e = blockIdx.x * blockDim.x + threadIdx.x;
    if (e < E) {
        int d = dst[e];
        int pos = g_rowptr[d] + atomicAdd(&g_fill[d], 1);
        g_col[pos] = src[e];
    }
}

// ---------------- aggregation ------------------------------------------------------
__device__ __forceinline__ float dot_leaky(float4 xs4, float4 xd4, float4 at4) {
    float t, p = 0.0f;
    t = xs4.x + xd4.x; t = t > 0.f ? t : NEG_SLOPE * t; p = fmaf(t, at4.x, p);
    t = xs4.y + xd4.y; t = t > 0.f ? t : NEG_SLOPE * t; p = fmaf(t, at4.y, p);
    t = xs4.z + xd4.z; t = t > 0.f ? t : NEG_SLOPE * t; p = fmaf(t, at4.z, p);
    t = xs4.w + xd4.w; t = t > 0.f ? t : NEG_SLOPE * t; p = fmaf(t, at4.w, p);
    return p;
}

__global__ __launch_bounds__(256) void agg_kernel(
    const float* __restrict__ att, const float* __restrict__ cb, int n)
{
    if (blockIdx.x == 0 && threadIdx.x < HDIM) {
        g_sum[threadIdx.x] = 0.0f;
        g_sumsq[threadIdx.x] = 0.0f;
    }
    int d = (blockIdx.x * blockDim.x + threadIdx.x) >> 5;
    int lane = threadIdx.x & 31;
    if (d >= n) return;

    float4 xd4 = *(const float4*)&g_xd[(size_t)d * 128 + lane * 4];
    float4 at4 = *(const float4*)&att[lane * 4];
    int e0 = g_rowptr[d], e1 = g_rowptr[d + 1];

    float den = 0.0f;
    float4 acc = make_float4(0.f, 0.f, 0.f, 0.f);

    int e = e0;
    for (; e + 2 <= e1; e += 2) {
        int s0 = g_col[e], s1 = g_col[e + 1];
        float4 a0 = *(const float4*)&g_xs[(size_t)s0 * 128 + lane * 4];
        float4 a1 = *(const float4*)&g_xs[(size_t)s1 * 128 + lane * 4];
        float p0 = dot_leaky(a0, xd4, at4);
        float p1 = dot_leaky(a1, xd4, at4);
#pragma unroll
        for (int o = 16; o; o >>= 1) {
            p0 += __shfl_xor_sync(0xffffffff, p0, o);
            p1 += __shfl_xor_sync(0xffffffff, p1, o);
        }
        float w0 = __expf(p0), w1 = __expf(p1);
        den += w0 + w1;
        acc.x = fmaf(w0, a0.x, fmaf(w1, a1.x, acc.x));
        acc.y = fmaf(w0, a0.y, fmaf(w1, a1.y, acc.y));
        acc.z = fmaf(w0, a0.z, fmaf(w1, a1.z, acc.z));
        acc.w = fmaf(w0, a0.w, fmaf(w1, a1.w, acc.w));
    }
    if (e < e1) {
        int s0 = g_col[e];
        float4 a0 = *(const float4*)&g_xs[(size_t)s0 * 128 + lane * 4];
        float p0 = dot_leaky(a0, xd4, at4);
#pragma unroll
        for (int o = 16; o; o >>= 1) p0 += __shfl_xor_sync(0xffffffff, p0, o);
        float w0 = __expf(p0);
        den += w0;
        acc.x = fmaf(w0, a0.x, acc.x);
        acc.y = fmaf(w0, a0.y, acc.y);
        acc.z = fmaf(w0, a0.z, acc.z);
        acc.w = fmaf(w0, a0.w, acc.w);
    }

    float inv = 1.0f / (den + 1e-16f);
    float4 cb4 = *(const float4*)&cb[lane * 4];
    float4 o;
    o.x = acc.x * inv + cb4.x;
    o.y = acc.y * inv + cb4.y;
    o.z = acc.z * inv + cb4.z;
    o.w = acc.w * inv + cb4.w;
    *(float4*)&g_acc[(size_t)d * 128 + lane * 4] = o;
}

// ---------------- BN stats / apply ---------------------------------------------------
__global__ __launch_bounds__(128) void bn_stats_kernel(int n)
{
    int h = threadIdx.x;
    float s = 0.0f, sq = 0.0f;
    for (int r = blockIdx.x; r < n; r += gridDim.x) {
        float v = g_h[(size_t)r * 128 + h];
        s += v; sq += v * v;
    }
    atomicAdd(&g_sum[h], s);
    atomicAdd(&g_sumsq[h], sq);
}
__global__ __launch_bounds__(256) void bn_apply_kernel(
    const float* __restrict__ gamma, const float* __restrict__ beta,
    float* __restrict__ out, int n)
{
    int i = blockIdx.x * blockDim.x + threadIdx.x;
    if (i >= n * HDIM) return;
    int h = i & 127;
    float inv_n = 1.0f / (float)n;
    float mu = g_sum[h] * inv_n;
    float var = g_sumsq[h] * inv_n - mu * mu;
    out[i] = (g_h[i] - mu) * rsqrtf(var + 1e-5f) * gamma[h] + beta[h];
}

// ---------------- host driver ---------------------------------------------------------
extern "C" void kernel_launch(void* const* d_in, const int* in_sizes, int n_in,
                              void* d_out, int out_size)
{
    const float* x     = (const float*)d_in[0];
    const int*   ei    = (const int*)  d_in[1];
    const float* Wl    = (const float*)d_in[2];
    const float* bl    = (const float*)d_in[3];
    const float* Wr    = (const float*)d_in[4];
    const float* br    = (const float*)d_in[5];
    const float* att   = (const float*)d_in[6];
    const float* cb    = (const float*)d_in[7];
    const float* Wlin  = (const float*)d_in[8];
    const float* blin  = (const float*)d_in[9];
    const float* gamma = (const float*)d_in[10];
    const float* beta  = (const float*)d_in[11];

    const int n = in_sizes[0] / HDIM;
    const int E = in_sizes[1] / 2;
    const int* src = ei;
    const int* dst = ei + E;

    void* p;
    cudaGetSymbolAddress(&p, g_acc); float* p_acc = (float*)p;
    cudaGetSymbolAddress(&p, g_xs);  float* p_xs  = (float*)p;
    cudaGetSymbolAddress(&p, g_xd);  float* p_xd  = (float*)p;
    cudaGetSymbolAddress(&p, g_h);   float* p_h   = (float*)p;

    cudaFuncSetAttribute(gemm_mma_kernel, cudaFuncAttributeMaxDynamicSharedMemorySize,
                         SM_TOTAL);

    const int elem_blocks = (n * HDIM + 255) / 256;
    const dim3 gemm_grid((n + 127) / 128, 2);
    const int agg_blocks  = (n + 7) / 8;
    const int e_blocks    = (E + 255) / 256;
    const int scan_blocks = (n + 1023) / 1024;

    prep_w_kernel<<<384, 256>>>(Wl, Wr, Wlin);
    csr_zero_kernel<<<(n + 255) / 256, 256>>>(n);
    csr_hist_kernel<<<e_blocks, 256>>>(dst, E);
    gemm_mma_kernel<<<gemm_grid, 256, SM_TOTAL>>>(x, 0, bl, p_xs, n, 0, nullptr, nullptr); // profiled
    csr_scanA_kernel<<<scan_blocks, 1024>>>(n);
    csr_scanC_kernel<<<scan_blocks, 1024>>>(n);
    csr_fill_kernel<<<e_blocks, 256>>>(src, dst, E);
    gemm_mma_kernel<<<gemm_grid, 256, SM_TOTAL>>>(x, 1, br, p_xd, n, 0, nullptr, nullptr);

    // layer 0
    agg_kernel<<<agg_blocks, 256>>>(att, cb, n);
    gemm_mma_kernel<<<gemm_grid, 256, SM_TOTAL>>>(p_acc, 2, blin, p_h, n, 1, nullptr, nullptr);
    bn_stats_kernel<<<512, 128>>>(n);

    // layer 1 (BN+relu of layer-0 output fused into A-staging)
    gemm_mma_kernel<<<gemm_grid, 256, SM_TOTAL>>>(p_h, 3, bl + HDIM, p_xs, n, 2, gamma, beta);
    gemm_mma_kernel<<<gemm_grid, 256, SM_TOTAL>>>(p_h, 4, br + HDIM, p_xd, n, 2, gamma, beta);
    agg_kernel<<<agg_blocks, 256>>>(att + HDIM, cb + HDIM, n);
    gemm_mma_kernel<<<gemm_grid, 256, SM_TOTAL>>>(p_acc, 5, blin + HDIM, p_h, n, 1, nullptr, nullptr);
    bn_stats_kernel<<<512, 128>>>(n);
    bn_apply_kernel<<<elem_blocks, 256>>>(gamma + HDIM, beta + HDIM, (float*)d_out, n);
}

// round 8
// speedup vs baseline: 2.1976x; 1.1485x over previous
#include <cuda_runtime.h>
#include <cuda_bf16.h>
#include <math.h>
#include <stdint.h>

#define NMAX 100000
#define HDIM 128
#define EMAX 625000
#define NEG_SLOPE 0.2f
#define KPAD 136                 // W image row stride (bf16 elems), 272B
#define APADB 80                 // A smem row stride bytes (40 bf16)

// ---------------- scratch ---------------------------------------------------------
__device__ float g_xs[NMAX * HDIM];
__device__ float g_xd[NMAX * HDIM];
__device__ float g_acc[NMAX * HDIM];
__device__ float g_h[NMAX * HDIM];
__device__ float g_sum[HDIM];
__device__ float g_sumsq[HDIM];
__device__ __align__(16) __nv_bfloat16 g_Wbf[6 * 2 * 128 * KPAD];  // [mat][hi/lo][n][k]

// CSR scratch
__device__ int g_deg[NMAX];
__device__ int g_fill[NMAX];
__device__ int g_rowptr[NMAX + 1];
__device__ int g_col[EMAX];
__device__ int g_blocksum[128];

// ---------------- helpers ----------------------------------------------------------
__device__ __forceinline__ uint32_t smem_to_u32(const void* p) {
    uint32_t a;
    asm("{ .reg .u64 t; cvta.to.shared.u64 t, %1; cvt.u32.u64 %0, t; }" : "=r"(a) : "l"(p));
    return a;
}
__device__ __forceinline__ void ldsm_x4(uint32_t& r0, uint32_t& r1, uint32_t& r2,
                                        uint32_t& r3, uint32_t addr) {
    asm volatile("ldmatrix.sync.aligned.m8n8.x4.shared.b16 {%0,%1,%2,%3}, [%4];"
                 : "=r"(r0), "=r"(r1), "=r"(r2), "=r"(r3) : "r"(addr));
}
__device__ __forceinline__ void mma_bf16(float* c, const uint32_t* a, const uint32_t* b) {
    asm volatile(
        "mma.sync.aligned.m16n8k16.row.col.f32.bf16.bf16.f32 "
        "{%0,%1,%2,%3}, {%4,%5,%6,%7}, {%8,%9}, {%0,%1,%2,%3};"
        : "+f"(c[0]), "+f"(c[1]), "+f"(c[2]), "+f"(c[3])
        : "r"(a[0]), "r"(a[1]), "r"(a[2]), "r"(a[3]), "r"(b[0]), "r"(b[1]));
}
__device__ __forceinline__ uint32_t pack_hi(float x, float y) {
    __nv_bfloat16 h0 = __float2bfloat16(x), h1 = __float2bfloat16(y);
    return (uint32_t)__bfloat16_as_ushort(h0) | ((uint32_t)__bfloat16_as_ushort(h1) << 16);
}
__device__ __forceinline__ uint32_t pack_lo(float x, float y) {
    __nv_bfloat16 h0 = __float2bfloat16(x), h1 = __float2bfloat16(y);
    __nv_bfloat16 l0 = __float2bfloat16(x - __bfloat162float(h0));
    __nv_bfloat16 l1 = __float2bfloat16(y - __bfloat162float(h1));
    return (uint32_t)__bfloat16_as_ushort(l0) | ((uint32_t)__bfloat16_as_ushort(l1) << 16);
}

// ---------------- prep: transpose + hi/lo split W ------------------------------------
__global__ void prep_w_kernel(const float* __restrict__ Wl, const float* __restrict__ Wr,
                              const float* __restrict__ Wlin) {
    int idx = blockIdx.x * blockDim.x + threadIdx.x;
    if (idx >= 6 * 128 * 128) return;
    int m = idx >> 14;
    int r = idx & 16383;
    int nrow = r >> 7;
    int k = r & 127;
    int layer = m / 3, which = m % 3;
    const float* W = (which == 0 ? Wl : which == 1 ? Wr : Wlin) + (size_t)layer * HDIM * HDIM;
    float w = W[k * 128 + nrow];
    __nv_bfloat16 h = __float2bfloat16(w);
    __nv_bfloat16 l = __float2bfloat16(w - __bfloat162float(h));
    g_Wbf[((size_t)(m * 2 + 0) * 128 + nrow) * KPAD + k] = h;
    g_Wbf[((size_t)(m * 2 + 1) * 128 + nrow) * KPAD + k] = l;
}

// ---------------- GEMM v4 (mma.sync bf16 split): Y = op(X) @ W + bias ----------------
// mode 0: plain    mode 1: Y = X + X@W + b (X != Y)    mode 2: X := BN+relu(X) first
// CTA tile 128 x 128, 256 threads, warps 4m x 2n, warp tile 32x64.
// B (hi+lo) fully smem-resident; A chunked k=32 with register prefetch pipeline.
#define SM4_AH 0
#define SM4_AL 10240
#define SM4_BH 20480
#define SM4_BL 55296
#define SM4_TOTAL 90112

__global__ __launch_bounds__(256, 2) void gemm_mma4_kernel(
    const float* __restrict__ X, int wimg, const float* __restrict__ bias,
    float* __restrict__ Y, int n, int mode,
    const float* __restrict__ bng, const float* __restrict__ bnb)
{
    extern __shared__ char smem[];
    __shared__ float s_scale[128];
    __shared__ float s_shift[128];
    const uint32_t sb = smem_to_u32(smem);
    const int tid = threadIdx.x;
    const int wid = tid >> 5;
    const int lane = tid & 31;
    const int row0 = blockIdx.x * 128;
    const int warp_m = wid & 3;      // 4 x 32 rows
    const int warp_n = wid >> 2;     // 2 x 64 cols

    if (mode == 2 && tid < 128) {
        float inv_n = 1.0f / (float)n;
        float mu = g_sum[tid] * inv_n;
        float var = g_sumsq[tid] * inv_n - mu * mu;
        float sc = bng[tid] * rsqrtf(var + 1e-5f);
        s_scale[tid] = sc;
        s_shift[tid] = bnb[tid] - mu * sc;
    }

    // stage full B [128 n][KPAD k] hi+lo (pre-swizzled layout, straight copy)
    {
        const uint4* gBh = (const uint4*)(g_Wbf + (size_t)(wimg * 2 + 0) * 128 * KPAD);
        const uint4* gBl = (const uint4*)(g_Wbf + (size_t)(wimg * 2 + 1) * 128 * KPAD);
        uint4* sBh = (uint4*)(smem + SM4_BH);
        uint4* sBl = (uint4*)(smem + SM4_BL);
        for (int f = tid; f < 2176; f += 256) {   // 34816B / 16
            sBh[f] = gBh[f];
            sBl[f] = gBl[f];
        }
    }

    // prefetch first A chunk (rows 0..127, k 0..31) into registers
    float4 pre[4];
#pragma unroll
    for (int i = 0; i < 4; i++) {
        int f = tid + i * 256;
        int row = f >> 3, c4 = (f & 7) * 4;
        int gr = row0 + row;
        pre[i] = (gr < n) ? *(const float4*)&X[(size_t)gr * 128 + c4]
                          : make_float4(0.f, 0.f, 0.f, 0.f);
    }
    __syncthreads();   // s_scale/s_shift + B staging visible to all

    float acc[2][8][4];
#pragma unroll
    for (int a = 0; a < 2; a++)
#pragma unroll
        for (int b = 0; b < 8; b++)
#pragma unroll
            for (int c = 0; c < 4; c++) acc[a][b][c] = 0.0f;

    // per-lane ldmatrix base addresses
    const uint32_t aAh = sb + SM4_AH + (warp_m * 32 + (lane & 15)) * APADB + (lane >> 4) * 16;
    const uint32_t aAl = aAh + (SM4_AL - SM4_AH);
    const uint32_t aBh = sb + SM4_BH + (warp_n * 64 + (lane & 7) + (lane >> 4) * 8) * (KPAD * 2)
                       + ((lane >> 3) & 1) * 16;
    const uint32_t aBl = aBh + (SM4_BL - SM4_BH);

    for (int kc = 0; kc < 128; kc += 32) {
        // store prefetched A chunk (with optional BN+relu) as hi/lo bf16
#pragma unroll
        for (int i = 0; i < 4; i++) {
            int f = tid + i * 256;
            int row = f >> 3, c4 = (f & 7) * 4;
            float4 v = pre[i];
            if (mode == 2) {
                int cc = kc + c4;
                v.x = fmaxf(0.f, fmaf(v.x, s_scale[cc],     s_shift[cc]));
                v.y = fmaxf(0.f, fmaf(v.y, s_scale[cc + 1], s_shift[cc + 1]));
                v.z = fmaxf(0.f, fmaf(v.z, s_scale[cc + 2], s_shift[cc + 2]));
                v.w = fmaxf(0.f, fmaf(v.w, s_scale[cc + 3], s_shift[cc + 3]));
            }
            *(uint2*)(smem + SM4_AH + row * APADB + c4 * 2) =
                make_uint2(pack_hi(v.x, v.y), pack_hi(v.z, v.w));
            *(uint2*)(smem + SM4_AL + row * APADB + c4 * 2) =
                make_uint2(pack_lo(v.x, v.y), pack_lo(v.z, v.w));
        }
        __syncthreads();

        // issue next chunk's loads now; latency overlaps the MMA phase below
        if (kc < 96) {
#pragma unroll
            for (int i = 0; i < 4; i++) {
                int f = tid + i * 256;
                int row = f >> 3, c4 = (f & 7) * 4;
                int gr = row0 + row;
                pre[i] = (gr < n) ? *(const float4*)&X[(size_t)gr * 128 + kc + 32 + c4]
                                  : make_float4(0.f, 0.f, 0.f, 0.f);
            }
        }

#pragma unroll
        for (int kk = 0; kk < 32; kk += 16) {
            uint32_t ah[2][4], al[2][4];
#pragma unroll
            for (int ms = 0; ms < 2; ms++) {
                uint32_t off = ms * 16 * APADB + kk * 2;
                ldsm_x4(ah[ms][0], ah[ms][1], ah[ms][2], ah[ms][3], aAh + off);
                ldsm_x4(al[ms][0], al[ms][1], al[ms][2], al[ms][3], aAl + off);
            }
#pragma unroll
            for (int nn = 0; nn < 4; nn++) {
                uint32_t bh2[4], bl2[4];
                uint32_t off = nn * 16 * (KPAD * 2) + (kc + kk) * 2;
                ldsm_x4(bh2[0], bh2[1], bh2[2], bh2[3], aBh + off);
                ldsm_x4(bl2[0], bl2[1], bl2[2], bl2[3], aBl + off);
#pragma unroll
                for (int ms = 0; ms < 2; ms++) {
                    mma_bf16(acc[ms][nn * 2],     ah[ms], bh2);       // hi*hi
                    mma_bf16(acc[ms][nn * 2],     al[ms], bh2);       // lo*hi
                    mma_bf16(acc[ms][nn * 2],     ah[ms], bl2);       // hi*lo
                    mma_bf16(acc[ms][nn * 2 + 1], ah[ms], bh2 + 2);
                    mma_bf16(acc[ms][nn * 2 + 1], al[ms], bh2 + 2);
                    mma_bf16(acc[ms][nn * 2 + 1], ah[ms], bl2 + 2);
                }
            }
        }
        if (kc < 96) __syncthreads();   // MMA done before next store phase overwrites A
    }

    // epilogue
    const int er0 = row0 + warp_m * 32 + (lane >> 2);
    const int ec0 = warp_n * 64 + (lane & 3) * 2;
#pragma unroll
    for (int ms = 0; ms < 2; ms++) {
#pragma unroll
        for (int ns = 0; ns < 8; ns++) {
            int r = er0 + ms * 16;
            int c = ec0 + ns * 8;
            float b0 = __ldg(&bias[c]), b1 = __ldg(&bias[c + 1]);
            if (r < n) {
                float2 o = make_float2(acc[ms][ns][0] + b0, acc[ms][ns][1] + b1);
                if (mode == 1) {
                    const float2 rv = *(const float2*)&X[(size_t)r * 128 + c];
                    o.x += rv.x; o.y += rv.y;
                }
                *(float2*)&Y[(size_t)r * 128 + c] = o;
            }
            if (r + 8 < n) {
                float2 o = make_float2(acc[ms][ns][2] + b0, acc[ms][ns][3] + b1);
                if (mode == 1) {
                    const float2 rv = *(const float2*)&X[(size_t)(r + 8) * 128 + c];
                    o.x += rv.x; o.y += rv.y;
                }
                *(float2*)&Y[(size_t)(r + 8) * 128 + c] = o;
            }
        }
    }
}

// ---------------- CSR build ------------------------------------------------------
__global__ void csr_zero_kernel(int n) {
    int i = blockIdx.x * blockDim.x + threadIdx.x;
    if (i < n) { g_deg[i] = 0; g_fill[i] = 0; }
}
__global__ void csr_hist_kernel(const int* __restrict__ dst, int E) {
    int e = blockIdx.x * blockDim.x + threadIdx.x;
    if (e < E) atomicAdd(&g_deg[dst[e]], 1);
}
__global__ void csr_scanA_kernel(int n) {
    __shared__ int s[1024];
    int t = threadIdx.x;
    int i = blockIdx.x * 1024 + t;
    int v = (i < n) ? g_deg[i] : 0;
    s[t] = v;
    __syncthreads();
#pragma unroll
    for (int off = 1; off < 1024; off <<= 1) {
        int x = (t >= off) ? s[t - off] : 0;
        __syncthreads();
        s[t] += x;
        __syncthreads();
    }
    if (i < n) g_rowptr[i + 1] = s[t];
    if (t == 1023) g_blocksum[blockIdx.x] = s[t];
    if (i == 0) g_rowptr[0] = 0;
}
__global__ void csr_scanC_kernel(int n) {
    __shared__ int s_off;
    int t = threadIdx.x;
    if (t < 32) {
        int b = blockIdx.x;
        int sum = 0;
        for (int i = t; i < b; i += 32) sum += g_blocksum[i];
#pragma unroll
        for (int o = 16; o; o >>= 1) sum += __shfl_xor_sync(0xffffffff, sum, o);
        if (t == 0) s_off = sum;
    }
    __syncthreads();
    int i = blockIdx.x * 1024 + t;
    if (i < n) g_rowptr[i + 1] += s_off;
}
__global__ void csr_fill_kernel(const int* __restrict__ src, const int* __restrict__ dst, int E) {
    int e = blockIdx.x * blockDim.x + threadIdx.x;
    if (e < E) {
        int d = dst[e];
        int pos = g_rowptr[d] + atomicAdd(&g_fill[d], 1);
        g_col[pos] = src[e];
    }
}

// ---------------- aggregation ------------------------------------------------------
__device__ __forceinline__ float dot_leaky(float4 xs4, float4 xd4, float4 at4) {
    float t, p = 0.0f;
    t = xs4.x + xd4.x; t = t > 0.f ? t : NEG_SLOPE * t; p = fmaf(t, at4.x, p);
    t = xs4.y + xd4.y; t = t > 0.f ? t : NEG_SLOPE * t; p = fmaf(t, at4.y, p);
    t = xs4.z + xd4.z; t = t > 0.f ? t : NEG_SLOPE * t; p = fmaf(t, at4.z, p);
    t = xs4.w + xd4.w; t = t > 0.f ? t : NEG_SLOPE * t; p = fmaf(t, at4.w, p);
    return p;
}

__global__ __launch_bounds__(256) void agg_kernel(
    const float* __restrict__ att, const float* __restrict__ cb, int n)
{
    if (blockIdx.x == 0 && threadIdx.x < HDIM) {
        g_sum[threadIdx.x] = 0.0f;
        g_sumsq[threadIdx.x] = 0.0f;
    }
    int d = (blockIdx.x * blockDim.x + threadIdx.x) >> 5;
    int lane = threadIdx.x & 31;
    if (d >= n) return;

    float4 xd4 = *(const float4*)&g_xd[(size_t)d * 128 + lane * 4];
    float4 at4 = *(const float4*)&att[lane * 4];
    int e0 = g_rowptr[d], e1 = g_rowptr[d + 1];

    float den = 0.0f;
    float4 acc = make_float4(0.f, 0.f, 0.f, 0.f);

    int e = e0;
    for (; e + 2 <= e1; e += 2) {
        int s0 = g_col[e], s1 = g_col[e + 1];
        float4 a0 = *(const float4*)&g_xs[(size_t)s0 * 128 + lane * 4];
        float4 a1 = *(const float4*)&g_xs[(size_t)s1 * 128 + lane * 4];
        float p0 = dot_leaky(a0, xd4, at4);
        float p1 = dot_leaky(a1, xd4, at4);
#pragma unroll
        for (int o = 16; o; o >>= 1) {
            p0 += __shfl_xor_sync(0xffffffff, p0, o);
            p1 += __shfl_xor_sync(0xffffffff, p1, o);
        }
        float w0 = __expf(p0), w1 = __expf(p1);
        den += w0 + w1;
        acc.x = fmaf(w0, a0.x, fmaf(w1, a1.x, acc.x));
        acc.y = fmaf(w0, a0.y, fmaf(w1, a1.y, acc.y));
        acc.z = fmaf(w0, a0.z, fmaf(w1, a1.z, acc.z));
        acc.w = fmaf(w0, a0.w, fmaf(w1, a1.w, acc.w));
    }
    if (e < e1) {
        int s0 = g_col[e];
        float4 a0 = *(const float4*)&g_xs[(size_t)s0 * 128 + lane * 4];
        float p0 = dot_leaky(a0, xd4, at4);
#pragma unroll
        for (int o = 16; o; o >>= 1) p0 += __shfl_xor_sync(0xffffffff, p0, o);
        float w0 = __expf(p0);
        den += w0;
        acc.x = fmaf(w0, a0.x, acc.x);
        acc.y = fmaf(w0, a0.y, acc.y);
        acc.z = fmaf(w0, a0.z, acc.z);
        acc.w = fmaf(w0, a0.w, acc.w);
    }

    float inv = 1.0f / (den + 1e-16f);
    float4 cb4 = *(const float4*)&cb[lane * 4];
    float4 o;
    o.x = acc.x * inv + cb4.x;
    o.y = acc.y * inv + cb4.y;
    o.z = acc.z * inv + cb4.z;
    o.w = acc.w * inv + cb4.w;
    *(float4*)&g_acc[(size_t)d * 128 + lane * 4] = o;
}

// ---------------- BN stats / apply ---------------------------------------------------
__global__ __launch_bounds__(128) void bn_stats_kernel(int n)
{
    int h = threadIdx.x;
    float s = 0.0f, sq = 0.0f;
    for (int r = blockIdx.x; r < n; r += gridDim.x) {
        float v = g_h[(size_t)r * 128 + h];
        s += v; sq += v * v;
    }
    atomicAdd(&g_sum[h], s);
    atomicAdd(&g_sumsq[h], sq);
}
__global__ __launch_bounds__(256) void bn_apply_kernel(
    const float* __restrict__ gamma, const float* __restrict__ beta,
    float* __restrict__ out, int n)
{
    int i = blockIdx.x * blockDim.x + threadIdx.x;
    if (i >= n * HDIM) return;
    int h = i & 127;
    float inv_n = 1.0f / (float)n;
    float mu = g_sum[h] * inv_n;
    float var = g_sumsq[h] * inv_n - mu * mu;
    out[i] = (g_h[i] - mu) * rsqrtf(var + 1e-5f) * gamma[h] + beta[h];
}

// ---------------- host driver ---------------------------------------------------------
extern "C" void kernel_launch(void* const* d_in, const int* in_sizes, int n_in,
                              void* d_out, int out_size)
{
    const float* x     = (const float*)d_in[0];
    const int*   ei    = (const int*)  d_in[1];
    const float* Wl    = (const float*)d_in[2];
    const float* bl    = (const float*)d_in[3];
    const float* Wr    = (const float*)d_in[4];
    const float* br    = (const float*)d_in[5];
    const float* att   = (const float*)d_in[6];
    const float* cb    = (const float*)d_in[7];
    const float* Wlin  = (const float*)d_in[8];
    const float* blin  = (const float*)d_in[9];
    const float* gamma = (const float*)d_in[10];
    const float* beta  = (const float*)d_in[11];

    const int n = in_sizes[0] / HDIM;
    const int E = in_sizes[1] / 2;
    const int* src = ei;
    const int* dst = ei + E;

    void* p;
    cudaGetSymbolAddress(&p, g_acc); float* p_acc = (float*)p;
    cudaGetSymbolAddress(&p, g_xs);  float* p_xs  = (float*)p;
    cudaGetSymbolAddress(&p, g_xd);  float* p_xd  = (float*)p;
    cudaGetSymbolAddress(&p, g_h);   float* p_h   = (float*)p;

    cudaFuncSetAttribute(gemm_mma4_kernel, cudaFuncAttributeMaxDynamicSharedMemorySize,
                         SM4_TOTAL);

    const int elem_blocks = (n * HDIM + 255) / 256;
    const int gemm_blocks = (n + 127) / 128;
    const int agg_blocks  = (n + 7) / 8;
    const int e_blocks    = (E + 255) / 256;
    const int scan_blocks = (n + 1023) / 1024;

    prep_w_kernel<<<384, 256>>>(Wl, Wr, Wlin);
    csr_zero_kernel<<<(n + 255) / 256, 256>>>(n);
    csr_hist_kernel<<<e_blocks, 256>>>(dst, E);
    gemm_mma4_kernel<<<gemm_blocks, 256, SM4_TOTAL>>>(x, 0, bl, p_xs, n, 0, nullptr, nullptr); // profiled
    csr_scanA_kernel<<<scan_blocks, 1024>>>(n);
    csr_scanC_kernel<<<scan_blocks, 1024>>>(n);
    csr_fill_kernel<<<e_blocks, 256>>>(src, dst, E);
    gemm_mma4_kernel<<<gemm_blocks, 256, SM4_TOTAL>>>(x, 1, br, p_xd, n, 0, nullptr, nullptr);

    // layer 0
    agg_kernel<<<agg_blocks, 256>>>(att, cb, n);
    gemm_mma4_kernel<<<gemm_blocks, 256, SM4_TOTAL>>>(p_acc, 2, blin, p_h, n, 1, nullptr, nullptr);
    bn_stats_kernel<<<512, 128>>>(n);

    // layer 1 (BN+relu of layer-0 output fused into A-staging)
    gemm_mma4_kernel<<<gemm_blocks, 256, SM4_TOTAL>>>(p_h, 3, bl + HDIM, p_xs, n, 2, gamma, beta);
    gemm_mma4_kernel<<<gemm_blocks, 256, SM4_TOTAL>>>(p_h, 4, br + HDIM, p_xd, n, 2, gamma, beta);
    agg_kernel<<<agg_blocks, 256>>>(att + HDIM, cb + HDIM, n);
    gemm_mma4_kernel<<<gemm_blocks, 256, SM4_TOTAL>>>(p_acc, 5, blin + HDIM, p_h, n, 1, nullptr, nullptr);
    bn_stats_kernel<<<512, 128>>>(n);
    bn_apply_kernel<<<elem_blocks, 256>>>(gamma + HDIM, beta + HDIM, (float*)d_out, n);
}

// round 9
// speedup vs baseline: 2.4128x; 1.0979x over previous
#include <cuda_runtime.h>
#include <cuda_bf16.h>
#include <math.h>
#include <stdint.h>

#define NMAX 100000
#define HDIM 128
#define EMAX 625000
#define NEG_SLOPE 0.2f
#define KPAD 136                 // W image row stride (bf16 elems), 272B
#define APADB 80                 // A smem row stride bytes (40 bf16)
#define WIMG_BYTES 34816         // one 128xKPAD bf16 image

// ---------------- scratch ---------------------------------------------------------
__device__ float g_xs[NMAX * HDIM];
__device__ float g_xd[NMAX * HDIM];
__device__ float g_acc[NMAX * HDIM];
__device__ float g_h[NMAX * HDIM];
__device__ float g_sum[HDIM];
__device__ float g_sumsq[HDIM];
__device__ __align__(16) __nv_bfloat16 g_Wbf[6 * 2 * 128 * KPAD];  // [mat][hi/lo][n][k]

// CSR scratch
__device__ int g_deg[NMAX];
__device__ int g_fill[NMAX];
__device__ int g_rowptr[NMAX + 1];
__device__ int g_col[EMAX];
__device__ int g_blocksum[128];

// ---------------- helpers ----------------------------------------------------------
__device__ __forceinline__ uint32_t smem_to_u32(const void* p) {
    uint32_t a;
    asm("{ .reg .u64 t; cvta.to.shared.u64 t, %1; cvt.u32.u64 %0, t; }" : "=r"(a) : "l"(p));
    return a;
}
__device__ __forceinline__ void ldsm_x4(uint32_t& r0, uint32_t& r1, uint32_t& r2,
                                        uint32_t& r3, uint32_t addr) {
    asm volatile("ldmatrix.sync.aligned.m8n8.x4.shared.b16 {%0,%1,%2,%3}, [%4];"
                 : "=r"(r0), "=r"(r1), "=r"(r2), "=r"(r3) : "r"(addr));
}
__device__ __forceinline__ void mma_bf16(float* c, const uint32_t* a, const uint32_t* b) {
    asm volatile(
        "mma.sync.aligned.m16n8k16.row.col.f32.bf16.bf16.f32 "
        "{%0,%1,%2,%3}, {%4,%5,%6,%7}, {%8,%9}, {%0,%1,%2,%3};"
        : "+f"(c[0]), "+f"(c[1]), "+f"(c[2]), "+f"(c[3])
        : "r"(a[0]), "r"(a[1]), "r"(a[2]), "r"(a[3]), "r"(b[0]), "r"(b[1]));
}
__device__ __forceinline__ uint32_t pack_hi(float x, float y) {
    __nv_bfloat16 h0 = __float2bfloat16(x), h1 = __float2bfloat16(y);
    return (uint32_t)__bfloat16_as_ushort(h0) | ((uint32_t)__bfloat16_as_ushort(h1) << 16);
}
__device__ __forceinline__ uint32_t pack_lo(float x, float y) {
    __nv_bfloat16 h0 = __float2bfloat16(x), h1 = __float2bfloat16(y);
    __nv_bfloat16 l0 = __float2bfloat16(x - __bfloat162float(h0));
    __nv_bfloat16 l1 = __float2bfloat16(y - __bfloat162float(h1));
    return (uint32_t)__bfloat16_as_ushort(l0) | ((uint32_t)__bfloat16_as_ushort(l1) << 16);
}

// ---------------- prep: transpose + hi/lo split W ------------------------------------
__global__ void prep_w_kernel(const float* __restrict__ Wl, const float* __restrict__ Wr,
                              const float* __restrict__ Wlin) {
    int idx = blockIdx.x * blockDim.x + threadIdx.x;
    if (idx >= 6 * 128 * 128) return;
    int m = idx >> 14;
    int r = idx & 16383;
    int nrow = r >> 7;
    int k = r & 127;
    int layer = m / 3, which = m % 3;
    const float* W = (which == 0 ? Wl : which == 1 ? Wr : Wlin) + (size_t)layer * HDIM * HDIM;
    float w = W[k * 128 + nrow];
    __nv_bfloat16 h = __float2bfloat16(w);
    __nv_bfloat16 l = __float2bfloat16(w - __bfloat162float(h));
    g_Wbf[((size_t)(m * 2 + 0) * 128 + nrow) * KPAD + k] = h;
    g_Wbf[((size_t)(m * 2 + 1) * 128 + nrow) * KPAD + k] = l;
}

// ---------------- dual GEMM: xs = f(X)@Wl + bl, xd = f(X)@Wr + br ---------------------
// f = identity (mode 0) or BN+relu per column (mode 2). 512 threads, tile 128x256.
#define DSM_AH 0
#define DSM_AL 10240
#define DSM_BH 20480
#define DSM_BL (DSM_BH + 2 * WIMG_BYTES)
#define DSM_TOTAL (DSM_BL + 2 * WIMG_BYTES)

__global__ __launch_bounds__(512, 1) void gemm_dual_kernel(
    const float* __restrict__ X, int wimgL, int wimgR,
    const float* __restrict__ biasL, const float* __restrict__ biasR,
    float* __restrict__ YL, float* __restrict__ YR, int n, int mode,
    const float* __restrict__ bng, const float* __restrict__ bnb)
{
    extern __shared__ char smem[];
    __shared__ float s_scale[128];
    __shared__ float s_shift[128];
    const uint32_t sb = smem_to_u32(smem);
    const int tid = threadIdx.x;
    const int wid = tid >> 5;
    const int lane = tid & 31;
    const int row0 = blockIdx.x * 128;
    const int warp_m = wid & 3;      // 4 x 32 rows
    const int warp_n = wid >> 2;     // 4 x 64 cols (0,1 -> Wl; 2,3 -> Wr)

    if (mode == 2 && tid < 128) {
        float inv_n = 1.0f / (float)n;
        float mu = g_sum[tid] * inv_n;
        float var = g_sumsq[tid] * inv_n - mu * mu;
        float sc = bng[tid] * rsqrtf(var + 1e-5f);
        s_scale[tid] = sc;
        s_shift[tid] = bnb[tid] - mu * sc;
    }

    // stage both B images (hi & lo): [Wl | Wr]
    {
        const uint4* gLh = (const uint4*)(g_Wbf + (size_t)(wimgL * 2 + 0) * 128 * KPAD);
        const uint4* gLl = (const uint4*)(g_Wbf + (size_t)(wimgL * 2 + 1) * 128 * KPAD);
        const uint4* gRh = (const uint4*)(g_Wbf + (size_t)(wimgR * 2 + 0) * 128 * KPAD);
        const uint4* gRl = (const uint4*)(g_Wbf + (size_t)(wimgR * 2 + 1) * 128 * KPAD);
        uint4* sBh = (uint4*)(smem + DSM_BH);
        uint4* sBl = (uint4*)(smem + DSM_BL);
        for (int f = tid; f < 2176; f += 512) {
            sBh[f] = gLh[f];
            sBh[f + 2176] = gRh[f];
            sBl[f] = gLl[f];
            sBl[f + 2176] = gRl[f];
        }
    }

    // prefetch first A chunk
    float4 pre[2];
#pragma unroll
    for (int i = 0; i < 2; i++) {
        int f = tid + i * 512;
        int row = f >> 3, c4 = (f & 7) * 4;
        int gr = row0 + row;
        pre[i] = (gr < n) ? *(const float4*)&X[(size_t)gr * 128 + c4]
                          : make_float4(0.f, 0.f, 0.f, 0.f);
    }
    __syncthreads();

    float acc[2][8][4];
#pragma unroll
    for (int a = 0; a < 2; a++)
#pragma unroll
        for (int b = 0; b < 8; b++)
#pragma unroll
            for (int c = 0; c < 4; c++) acc[a][b][c] = 0.0f;

    const uint32_t aAh = sb + DSM_AH + (warp_m * 32 + (lane & 15)) * APADB + (lane >> 4) * 16;
    const uint32_t aAl = aAh + (DSM_AL - DSM_AH);
    const uint32_t aBh = sb + DSM_BH + (warp_n >> 1) * WIMG_BYTES
                       + ((warp_n & 1) * 64 + (lane & 7) + (lane >> 4) * 8) * (KPAD * 2)
                       + ((lane >> 3) & 1) * 16;
    const uint32_t aBl = aBh + (DSM_BL - DSM_BH);

    for (int kc = 0; kc < 128; kc += 32) {
#pragma unroll
        for (int i = 0; i < 2; i++) {
            int f = tid + i * 512;
            int row = f >> 3, c4 = (f & 7) * 4;
            float4 v = pre[i];
            if (mode == 2) {
                int cc = kc + c4;
                v.x = fmaxf(0.f, fmaf(v.x, s_scale[cc],     s_shift[cc]));
                v.y = fmaxf(0.f, fmaf(v.y, s_scale[cc + 1], s_shift[cc + 1]));
                v.z = fmaxf(0.f, fmaf(v.z, s_scale[cc + 2], s_shift[cc + 2]));
                v.w = fmaxf(0.f, fmaf(v.w, s_scale[cc + 3], s_shift[cc + 3]));
            }
            *(uint2*)(smem + DSM_AH + row * APADB + c4 * 2) =
                make_uint2(pack_hi(v.x, v.y), pack_hi(v.z, v.w));
            *(uint2*)(smem + DSM_AL + row * APADB + c4 * 2) =
                make_uint2(pack_lo(v.x, v.y), pack_lo(v.z, v.w));
        }
        __syncthreads();

        if (kc < 96) {
#pragma unroll
            for (int i = 0; i < 2; i++) {
                int f = tid + i * 512;
                int row = f >> 3, c4 = (f & 7) * 4;
                int gr = row0 + row;
                pre[i] = (gr < n) ? *(const float4*)&X[(size_t)gr * 128 + kc + 32 + c4]
                                  : make_float4(0.f, 0.f, 0.f, 0.f);
            }
        }

#pragma unroll
        for (int kk = 0; kk < 32; kk += 16) {
            uint32_t ah[2][4], al[2][4];
#pragma unroll
            for (int ms = 0; ms < 2; ms++) {
                uint32_t off = ms * 16 * APADB + kk * 2;
                ldsm_x4(ah[ms][0], ah[ms][1], ah[ms][2], ah[ms][3], aAh + off);
                ldsm_x4(al[ms][0], al[ms][1], al[ms][2], al[ms][3], aAl + off);
            }
#pragma unroll
            for (int nn = 0; nn < 4; nn++) {
                uint32_t bh2[4], bl2[4];
                uint32_t off = nn * 16 * (KPAD * 2) + (kc + kk) * 2;
                ldsm_x4(bh2[0], bh2[1], bh2[2], bh2[3], aBh + off);
                ldsm_x4(bl2[0], bl2[1], bl2[2], bl2[3], aBl + off);
#pragma unroll
                for (int ms = 0; ms < 2; ms++) {
                    mma_bf16(acc[ms][nn * 2],     ah[ms], bh2);
                    mma_bf16(acc[ms][nn * 2],     al[ms], bh2);
                    mma_bf16(acc[ms][nn * 2],     ah[ms], bl2);
                    mma_bf16(acc[ms][nn * 2 + 1], ah[ms], bh2 + 2);
                    mma_bf16(acc[ms][nn * 2 + 1], al[ms], bh2 + 2);
                    mma_bf16(acc[ms][nn * 2 + 1], ah[ms], bl2 + 2);
                }
            }
        }
        if (kc < 96) __syncthreads();
    }

    // epilogue: warp_n<2 -> YL (cols (warp_n&1)*64..), else YR
    float* Y = (warp_n < 2) ? YL : YR;
    const float* bias = (warp_n < 2) ? biasL : biasR;
    const int er0 = row0 + warp_m * 32 + (lane >> 2);
    const int ec0 = (warp_n & 1) * 64 + (lane & 3) * 2;
#pragma unroll
    for (int ms = 0; ms < 2; ms++) {
#pragma unroll
        for (int ns = 0; ns < 8; ns++) {
            int r = er0 + ms * 16;
            int c = ec0 + ns * 8;
            float b0 = __ldg(&bias[c]), b1 = __ldg(&bias[c + 1]);
            if (r < n)
                *(float2*)&Y[(size_t)r * 128 + c] =
                    make_float2(acc[ms][ns][0] + b0, acc[ms][ns][1] + b1);
            if (r + 8 < n)
                *(float2*)&Y[(size_t)(r + 8) * 128 + c] =
                    make_float2(acc[ms][ns][2] + b0, acc[ms][ns][3] + b1);
        }
    }
}

// ---------------- GEMM v4 (single, used for residual mode): Y = X + X@W + b ----------
#define SM4_AH 0
#define SM4_AL 10240
#define SM4_BH 20480
#define SM4_BL 55296
#define SM4_TOTAL 90112

__global__ __launch_bounds__(256, 2) void gemm_mma4_kernel(
    const float* __restrict__ X, int wimg, const float* __restrict__ bias,
    float* __restrict__ Y, int n)
{
    extern __shared__ char smem[];
    const uint32_t sb = smem_to_u32(smem);
    const int tid = threadIdx.x;
    const int wid = tid >> 5;
    const int lane = tid & 31;
    const int row0 = blockIdx.x * 128;
    const int warp_m = wid & 3;
    const int warp_n = wid >> 2;

    {
        const uint4* gBh = (const uint4*)(g_Wbf + (size_t)(wimg * 2 + 0) * 128 * KPAD);
        const uint4* gBl = (const uint4*)(g_Wbf + (size_t)(wimg * 2 + 1) * 128 * KPAD);
        uint4* sBh = (uint4*)(smem + SM4_BH);
        uint4* sBl = (uint4*)(smem + SM4_BL);
        for (int f = tid; f < 2176; f += 256) {
            sBh[f] = gBh[f];
            sBl[f] = gBl[f];
        }
    }

    float4 pre[4];
#pragma unroll
    for (int i = 0; i < 4; i++) {
        int f = tid + i * 256;
        int row = f >> 3, c4 = (f & 7) * 4;
        int gr = row0 + row;
        pre[i] = (gr < n) ? *(const float4*)&X[(size_t)gr * 128 + c4]
                          : make_float4(0.f, 0.f, 0.f, 0.f);
    }
    __syncthreads();

    float acc[2][8][4];
#pragma unroll
    for (int a = 0; a < 2; a++)
#pragma unroll
        for (int b = 0; b < 8; b++)
#pragma unroll
            for (int c = 0; c < 4; c++) acc[a][b][c] = 0.0f;

    const uint32_t aAh = sb + SM4_AH + (warp_m * 32 + (lane & 15)) * APADB + (lane >> 4) * 16;
    const uint32_t aAl = aAh + (SM4_AL - SM4_AH);
    const uint32_t aBh = sb + SM4_BH + (warp_n * 64 + (lane & 7) + (lane >> 4) * 8) * (KPAD * 2)
                       + ((lane >> 3) & 1) * 16;
    const uint32_t aBl = aBh + (SM4_BL - SM4_BH);

    for (int kc = 0; kc < 128; kc += 32) {
#pragma unroll
        for (int i = 0; i < 4; i++) {
            int f = tid + i * 256;
            int row = f >> 3, c4 = (f & 7) * 4;
            float4 v = pre[i];
            *(uint2*)(smem + SM4_AH + row * APADB + c4 * 2) =
                make_uint2(pack_hi(v.x, v.y), pack_hi(v.z, v.w));
            *(uint2*)(smem + SM4_AL + row * APADB + c4 * 2) =
                make_uint2(pack_lo(v.x, v.y), pack_lo(v.z, v.w));
        }
        __syncthreads();

        if (kc < 96) {
#pragma unroll
            for (int i = 0; i < 4; i++) {
                int f = tid + i * 256;
                int row = f >> 3, c4 = (f & 7) * 4;
                int gr = row0 + row;
                pre[i] = (gr < n) ? *(const float4*)&X[(size_t)gr * 128 + kc + 32 + c4]
                                  : make_float4(0.f, 0.f, 0.f, 0.f);
            }
        }

#pragma unroll
        for (int kk = 0; kk < 32; kk += 16) {
            uint32_t ah[2][4], al[2][4];
#pragma unroll
            for (int ms = 0; ms < 2; ms++) {
                uint32_t off = ms * 16 * APADB + kk * 2;
                ldsm_x4(ah[ms][0], ah[ms][1], ah[ms][2], ah[ms][3], aAh + off);
                ldsm_x4(al[ms][0], al[ms][1], al[ms][2], al[ms][3], aAl + off);
            }
#pragma unroll
            for (int nn = 0; nn < 4; nn++) {
                uint32_t bh2[4], bl2[4];
                uint32_t off = nn * 16 * (KPAD * 2) + (kc + kk) * 2;
                ldsm_x4(bh2[0], bh2[1], bh2[2], bh2[3], aBh + off);
                ldsm_x4(bl2[0], bl2[1], bl2[2], bl2[3], aBl + off);
#pragma unroll
                for (int ms = 0; ms < 2; ms++) {
                    mma_bf16(acc[ms][nn * 2],     ah[ms], bh2);
                    mma_bf16(acc[ms][nn * 2],     al[ms], bh2);
                    mma_bf16(acc[ms][nn * 2],     ah[ms], bl2);
                    mma_bf16(acc[ms][nn * 2 + 1], ah[ms], bh2 + 2);
                    mma_bf16(acc[ms][nn * 2 + 1], al[ms], bh2 + 2);
                    mma_bf16(acc[ms][nn * 2 + 1], ah[ms], bl2 + 2);
                }
            }
        }
        if (kc < 96) __syncthreads();
    }

    const int er0 = row0 + warp_m * 32 + (lane >> 2);
    const int ec0 = warp_n * 64 + (lane & 3) * 2;
#pragma unroll
    for (int ms = 0; ms < 2; ms++) {
#pragma unroll
        for (int ns = 0; ns < 8; ns++) {
            int r = er0 + ms * 16;
            int c = ec0 + ns * 8;
            float b0 = __ldg(&bias[c]), b1 = __ldg(&bias[c + 1]);
            if (r < n) {
                const float2 rv = *(const float2*)&X[(size_t)r * 128 + c];
                *(float2*)&Y[(size_t)r * 128 + c] =
                    make_float2(acc[ms][ns][0] + b0 + rv.x, acc[ms][ns][1] + b1 + rv.y);
            }
            if (r + 8 < n) {
                const float2 rv = *(const float2*)&X[(size_t)(r + 8) * 128 + c];
                *(float2*)&Y[(size_t)(r + 8) * 128 + c] =
                    make_float2(acc[ms][ns][2] + b0 + rv.x, acc[ms][ns][3] + b1 + rv.y);
            }
        }
    }
}

// ---------------- CSR build ------------------------------------------------------
__global__ void csr_zero_kernel(int n) {
    int i = blockIdx.x * blockDim.x + threadIdx.x;
    if (i < n) { g_deg[i] = 0; g_fill[i] = 0; }
}
__global__ void csr_hist_kernel(const int* __restrict__ dst, int E) {
    int e = blockIdx.x * blockDim.x + threadIdx.x;
    if (e < E) atomicAdd(&g_deg[dst[e]], 1);
}
__global__ void csr_scanA_kernel(int n) {
    __shared__ int s[1024];
    int t = threadIdx.x;
    int i = blockIdx.x * 1024 + t;
    int v = (i < n) ? g_deg[i] : 0;
    s[t] = v;
    __syncthreads();
#pragma unroll
    for (int off = 1; off < 1024; off <<= 1) {
        int x = (t >= off) ? s[t - off] : 0;
        __syncthreads();
        s[t] += x;
        __syncthreads();
    }
    if (i < n) g_rowptr[i + 1] = s[t];
    if (t == 1023) g_blocksum[blockIdx.x] = s[t];
    if (i == 0) g_rowptr[0] = 0;
}
__global__ void csr_scanC_kernel(int n) {
    __shared__ int s_off;
    int t = threadIdx.x;
    if (t < 32) {
        int b = blockIdx.x;
        int sum = 0;
        for (int i = t; i < b; i += 32) sum += g_blocksum[i];
#pragma unroll
        for (int o = 16; o; o >>= 1) sum += __shfl_xor_sync(0xffffffff, sum, o);
        if (t == 0) s_off = sum;
    }
    __syncthreads();
    int i = blockIdx.x * 1024 + t;
    if (i < n) g_rowptr[i + 1] += s_off;
}
__global__ void csr_fill_kernel(const int* __restrict__ src, const int* __restrict__ dst, int E) {
    int e = blockIdx.x * blockDim.x + threadIdx.x;
    if (e < E) {
        int d = dst[e];
        int pos = g_rowptr[d] + atomicAdd(&g_fill[d], 1);
        g_col[pos] = src[e];
    }
}

// ---------------- aggregation: warp per node, 4-way pipelined --------------------
__device__ __forceinline__ float dot_leaky(float4 xs4, float4 xd4, float4 at4) {
    float t, p = 0.0f;
    t = xs4.x + xd4.x; t = t > 0.f ? t : NEG_SLOPE * t; p = fmaf(t, at4.x, p);
    t = xs4.y + xd4.y; t = t > 0.f ? t : NEG_SLOPE * t; p = fmaf(t, at4.y, p);
    t = xs4.z + xd4.z; t = t > 0.f ? t : NEG_SLOPE * t; p = fmaf(t, at4.z, p);
    t = xs4.w + xd4.w; t = t > 0.f ? t : NEG_SLOPE * t; p = fmaf(t, at4.w, p);
    return p;
}

__global__ __launch_bounds__(256) void agg_kernel(
    const float* __restrict__ att, const float* __restrict__ cb, int n)
{
    if (blockIdx.x == 0 && threadIdx.x < HDIM) {
        g_sum[threadIdx.x] = 0.0f;
        g_sumsq[threadIdx.x] = 0.0f;
    }
    int d = (blockIdx.x * blockDim.x + threadIdx.x) >> 5;
    int lane = threadIdx.x & 31;
    if (d >= n) return;

    float4 xd4 = *(const float4*)&g_xd[(size_t)d * 128 + lane * 4];
    float4 at4 = *(const float4*)&att[lane * 4];
    int e0 = g_rowptr[d], e1 = g_rowptr[d + 1];

    float den = 0.0f;
    float4 acc = make_float4(0.f, 0.f, 0.f, 0.f);

    int e = e0;
    for (; e + 4 <= e1; e += 4) {
        int s0 = g_col[e], s1 = g_col[e + 1], s2 = g_col[e + 2], s3 = g_col[e + 3];
        float4 a0 = *(const float4*)&g_xs[(size_t)s0 * 128 + lane * 4];
        float4 a1 = *(const float4*)&g_xs[(size_t)s1 * 128 + lane * 4];
        float4 a2 = *(const float4*)&g_xs[(size_t)s2 * 128 + lane * 4];
        float4 a3 = *(const float4*)&g_xs[(size_t)s3 * 128 + lane * 4];
        float p0 = dot_leaky(a0, xd4, at4);
        float p1 = dot_leaky(a1, xd4, at4);
        float p2 = dot_leaky(a2, xd4, at4);
        float p3 = dot_leaky(a3, xd4, at4);
#pragma unroll
        for (int o = 16; o; o >>= 1) {
            p0 += __shfl_xor_sync(0xffffffff, p0, o);
            p1 += __shfl_xor_sync(0xffffffff, p1, o);
            p2 += __shfl_xor_sync(0xffffffff, p2, o);
            p3 += __shfl_xor_sync(0xffffffff, p3, o);
        }
        float w0 = __expf(p0), w1 = __expf(p1), w2 = __expf(p2), w3 = __expf(p3);
        den += (w0 + w1) + (w2 + w3);
        acc.x = fmaf(w0, a0.x, fmaf(w1, a1.x, fmaf(w2, a2.x, fmaf(w3, a3.x, acc.x))));
        acc.y = fmaf(w0, a0.y, fmaf(w1, a1.y, fmaf(w2, a2.y, fmaf(w3, a3.y, acc.y))));
        acc.z = fmaf(w0, a0.z, fmaf(w1, a1.z, fmaf(w2, a2.z, fmaf(w3, a3.z, acc.z))));
        acc.w = fmaf(w0, a0.w, fmaf(w1, a1.w, fmaf(w2, a2.w, fmaf(w3, a3.w, acc.w))));
    }
    for (; e < e1; e++) {
        int s0 = g_col[e];
        float4 a0 = *(const float4*)&g_xs[(size_t)s0 * 128 + lane * 4];
        float p0 = dot_leaky(a0, xd4, at4);
#pragma unroll
        for (int o = 16; o; o >>= 1) p0 += __shfl_xor_sync(0xffffffff, p0, o);
        float w0 = __expf(p0);
        den += w0;
        acc.x = fmaf(w0, a0.x, acc.x);
        acc.y = fmaf(w0, a0.y, acc.y);
        acc.z = fmaf(w0, a0.z, acc.z);
        acc.w = fmaf(w0, a0.w, acc.w);
    }

    float inv = 1.0f / (den + 1e-16f);
    float4 cb4 = *(const float4*)&cb[lane * 4];
    float4 o;
    o.x = acc.x * inv + cb4.x;
    o.y = acc.y * inv + cb4.y;
    o.z = acc.z * inv + cb4.z;
    o.w = acc.w * inv + cb4.w;
    *(float4*)&g_acc[(size_t)d * 128 + lane * 4] = o;
}

// ---------------- BN stats / apply ---------------------------------------------------
__global__ __launch_bounds__(128) void bn_stats_kernel(int n)
{
    int h = threadIdx.x;
    float s = 0.0f, sq = 0.0f;
    for (int r = blockIdx.x; r < n; r += gridDim.x) {
        float v = g_h[(size_t)r * 128 + h];
        s += v; sq += v * v;
    }
    atomicAdd(&g_sum[h], s);
    atomicAdd(&g_sumsq[h], sq);
}
__global__ __launch_bounds__(256) void bn_apply_kernel(
    const float* __restrict__ gamma, const float* __restrict__ beta,
    float* __restrict__ out, int n)
{
    int i = blockIdx.x * blockDim.x + threadIdx.x;
    if (i >= n * HDIM) return;
    int h = i & 127;
    float inv_n = 1.0f / (float)n;
    float mu = g_sum[h] * inv_n;
    float var = g_sumsq[h] * inv_n - mu * mu;
    out[i] = (g_h[i] - mu) * rsqrtf(var + 1e-5f) * gamma[h] + beta[h];
}

// ---------------- host driver ---------------------------------------------------------
extern "C" void kernel_launch(void* const* d_in, const int* in_sizes, int n_in,
                              void* d_out, int out_size)
{
    const float* x     = (const float*)d_in[0];
    const int*   ei    = (const int*)  d_in[1];
    const float* Wl    = (const float*)d_in[2];
    const float* bl    = (const float*)d_in[3];
    const float* Wr    = (const float*)d_in[4];
    const float* br    = (const float*)d_in[5];
    const float* att   = (const float*)d_in[6];
    const float* cb    = (const float*)d_in[7];
    const float* Wlin  = (const float*)d_in[8];
    const float* blin  = (const float*)d_in[9];
    const float* gamma = (const float*)d_in[10];
    const float* beta  = (const float*)d_in[11];

    const int n = in_sizes[0] / HDIM;
    const int E = in_sizes[1] / 2;
    const int* src = ei;
    const int* dst = ei + E;

    void* p;
    cudaGetSymbolAddress(&p, g_acc); float* p_acc = (float*)p;
    cudaGetSymbolAddress(&p, g_xs);  float* p_xs  = (float*)p;
    cudaGetSymbolAddress(&p, g_xd);  float* p_xd  = (float*)p;
    cudaGetSymbolAddress(&p, g_h);   float* p_h   = (float*)p;

    cudaFuncSetAttribute(gemm_mma4_kernel, cudaFuncAttributeMaxDynamicSharedMemorySize,
                         SM4_TOTAL);
    cudaFuncSetAttribute(gemm_dual_kernel, cudaFuncAttributeMaxDynamicSharedMemorySize,
                         DSM_TOTAL);

    const int elem_blocks = (n * HDIM + 255) / 256;
    const int gemm_blocks = (n + 127) / 128;
    const int agg_blocks  = (n + 7) / 8;
    const int e_blocks    = (E + 255) / 256;
    const int scan_blocks = (n + 1023) / 1024;

    prep_w_kernel<<<384, 256>>>(Wl, Wr, Wlin);
    csr_zero_kernel<<<(n + 255) / 256, 256>>>(n);
    csr_hist_kernel<<<e_blocks, 256>>>(dst, E);
    gemm_dual_kernel<<<gemm_blocks, 512, DSM_TOTAL>>>(x, 0, 1, bl, br, p_xs, p_xd, n, 0,
                                                      nullptr, nullptr);  // profiled (4th)
    csr_scanA_kernel<<<scan_blocks, 1024>>>(n);
    csr_scanC_kernel<<<scan_blocks, 1024>>>(n);
    csr_fill_kernel<<<e_blocks, 256>>>(src, dst, E);

    // layer 0
    agg_kernel<<<agg_blocks, 256>>>(att, cb, n);
    gemm_mma4_kernel<<<gemm_blocks, 256, SM4_TOTAL>>>(p_acc, 2, blin, p_h, n);
    bn_stats_kernel<<<512, 128>>>(n);

    // layer 1 (BN+relu of layer-0 output fused into dual A-staging)
    gemm_dual_kernel<<<gemm_blocks, 512, DSM_TOTAL>>>(p_h, 3, 4, bl + HDIM, br + HDIM,
                                                      p_xs, p_xd, n, 2, gamma, beta);
    agg_kernel<<<agg_blocks, 256>>>(att + HDIM, cb + HDIM, n);
    gemm_mma4_kernel<<<gemm_blocks, 256, SM4_TOTAL>>>(p_acc, 5, blin + HDIM, p_h, n);
    bn_stats_kernel<<<512, 128>>>(n);
    bn_apply_kernel<<<elem_blocks, 256>>>(gamma + HDIM, beta + HDIM, (float*)d_out, n);
}

// round 10
// speedup vs baseline: 2.8732x; 1.1908x over previous
#include <cuda_runtime.h>
#include <cuda_bf16.h>
#include <math.h>
#include <stdint.h>

#define NMAX 100000
#define HDIM 128
#define EMAX 625000
#define NEG_SLOPE 0.2f
#define KPAD 136                 // W image row stride (bf16 elems), 272B
#define APADB 80                 // A smem row stride bytes (40 bf16)
#define WIMG_BYTES 34816         // one 128xKPAD bf16 image

// ---------------- scratch ---------------------------------------------------------
__device__ float g_xs[NMAX * HDIM];
__device__ float g_xd[NMAX * HDIM];
__device__ float g_acc[NMAX * HDIM];
__device__ float g_h[NMAX * HDIM];
__device__ float g_sum[HDIM];
__device__ float g_sumsq[HDIM];
__device__ __align__(16) __nv_bfloat16 g_Wbf[6 * 2 * 128 * KPAD];  // [mat][hi/lo][n][k]

// CSR scratch
__device__ int g_deg[NMAX];
__device__ int g_fill[NMAX];
__device__ int g_rowptr[NMAX + 1];
__device__ int g_col[EMAX];
__device__ int g_blocksum[128];

// ---------------- helpers ----------------------------------------------------------
__device__ __forceinline__ uint32_t smem_to_u32(const void* p) {
    uint32_t a;
    asm("{ .reg .u64 t; cvta.to.shared.u64 t, %1; cvt.u32.u64 %0, t; }" : "=r"(a) : "l"(p));
    return a;
}
__device__ __forceinline__ void ldsm_x4(uint32_t& r0, uint32_t& r1, uint32_t& r2,
                                        uint32_t& r3, uint32_t addr) {
    asm volatile("ldmatrix.sync.aligned.m8n8.x4.shared.b16 {%0,%1,%2,%3}, [%4];"
                 : "=r"(r0), "=r"(r1), "=r"(r2), "=r"(r3) : "r"(addr));
}
__device__ __forceinline__ void mma_bf16(float* c, const uint32_t* a, const uint32_t* b) {
    asm volatile(
        "mma.sync.aligned.m16n8k16.row.col.f32.bf16.bf16.f32 "
        "{%0,%1,%2,%3}, {%4,%5,%6,%7}, {%8,%9}, {%0,%1,%2,%3};"
        : "+f"(c[0]), "+f"(c[1]), "+f"(c[2]), "+f"(c[3])
        : "r"(a[0]), "r"(a[1]), "r"(a[2]), "r"(a[3]), "r"(b[0]), "r"(b[1]));
}
__device__ __forceinline__ uint32_t pack_hi(float x, float y) {
    __nv_bfloat16 h0 = __float2bfloat16(x), h1 = __float2bfloat16(y);
    return (uint32_t)__bfloat16_as_ushort(h0) | ((uint32_t)__bfloat16_as_ushort(h1) << 16);
}
__device__ __forceinline__ uint32_t pack_lo(float x, float y) {
    __nv_bfloat16 h0 = __float2bfloat16(x), h1 = __float2bfloat16(y);
    __nv_bfloat16 l0 = __float2bfloat16(x - __bfloat162float(h0));
    __nv_bfloat16 l1 = __float2bfloat16(y - __bfloat162float(h1));
    return (uint32_t)__bfloat16_as_ushort(l0) | ((uint32_t)__bfloat16_as_ushort(l1) << 16);
}

// ---------------- prep: W transpose/split + CSR zero (merged) -------------------------
__global__ void prep_w_kernel(const float* __restrict__ Wl, const float* __restrict__ Wr,
                              const float* __restrict__ Wlin, int n) {
    int idx = blockIdx.x * blockDim.x + threadIdx.x;
    if (idx < n) { g_deg[idx] = 0; g_fill[idx] = 0; }
    if (idx >= 6 * 128 * 128) return;
    int m = idx >> 14;
    int r = idx & 16383;
    int nrow = r >> 7;
    int k = r & 127;
    int layer = m / 3, which = m % 3;
    const float* W = (which == 0 ? Wl : which == 1 ? Wr : Wlin) + (size_t)layer * HDIM * HDIM;
    float w = W[k * 128 + nrow];
    __nv_bfloat16 h = __float2bfloat16(w);
    __nv_bfloat16 l = __float2bfloat16(w - __bfloat162float(h));
    g_Wbf[((size_t)(m * 2 + 0) * 128 + nrow) * KPAD + k] = h;
    g_Wbf[((size_t)(m * 2 + 1) * 128 + nrow) * KPAD + k] = l;
}

// ---------------- dual GEMM: xs = f(X)@Wl + bl, xd = f(X)@Wr + br ---------------------
#define DSM_AH 0
#define DSM_AL 10240
#define DSM_BH 20480
#define DSM_BL (DSM_BH + 2 * WIMG_BYTES)
#define DSM_TOTAL (DSM_BL + 2 * WIMG_BYTES)

__global__ __launch_bounds__(512, 1) void gemm_dual_kernel(
    const float* __restrict__ X, int wimgL, int wimgR,
    const float* __restrict__ biasL, const float* __restrict__ biasR,
    float* __restrict__ YL, float* __restrict__ YR, int n, int mode,
    const float* __restrict__ bng, const float* __restrict__ bnb)
{
    extern __shared__ char smem[];
    __shared__ float s_scale[128];
    __shared__ float s_shift[128];
    const uint32_t sb = smem_to_u32(smem);
    const int tid = threadIdx.x;
    const int wid = tid >> 5;
    const int lane = tid & 31;
    const int row0 = blockIdx.x * 128;
    const int warp_m = wid & 3;
    const int warp_n = wid >> 2;

    if (mode == 2 && tid < 128) {
        float inv_n = 1.0f / (float)n;
        float mu = g_sum[tid] * inv_n;
        float var = g_sumsq[tid] * inv_n - mu * mu;
        float sc = bng[tid] * rsqrtf(var + 1e-5f);
        s_scale[tid] = sc;
        s_shift[tid] = bnb[tid] - mu * sc;
    }

    {
        const uint4* gLh = (const uint4*)(g_Wbf + (size_t)(wimgL * 2 + 0) * 128 * KPAD);
        const uint4* gLl = (const uint4*)(g_Wbf + (size_t)(wimgL * 2 + 1) * 128 * KPAD);
        const uint4* gRh = (const uint4*)(g_Wbf + (size_t)(wimgR * 2 + 0) * 128 * KPAD);
        const uint4* gRl = (const uint4*)(g_Wbf + (size_t)(wimgR * 2 + 1) * 128 * KPAD);
        uint4* sBh = (uint4*)(smem + DSM_BH);
        uint4* sBl = (uint4*)(smem + DSM_BL);
        for (int f = tid; f < 2176; f += 512) {
            sBh[f] = gLh[f];
            sBh[f + 2176] = gRh[f];
            sBl[f] = gLl[f];
            sBl[f + 2176] = gRl[f];
        }
    }

    float4 pre[2];
#pragma unroll
    for (int i = 0; i < 2; i++) {
        int f = tid + i * 512;
        int row = f >> 3, c4 = (f & 7) * 4;
        int gr = row0 + row;
        pre[i] = (gr < n) ? *(const float4*)&X[(size_t)gr * 128 + c4]
                          : make_float4(0.f, 0.f, 0.f, 0.f);
    }
    __syncthreads();

    float acc[2][8][4];
#pragma unroll
    for (int a = 0; a < 2; a++)
#pragma unroll
        for (int b = 0; b < 8; b++)
#pragma unroll
            for (int c = 0; c < 4; c++) acc[a][b][c] = 0.0f;

    const uint32_t aAh = sb + DSM_AH + (warp_m * 32 + (lane & 15)) * APADB + (lane >> 4) * 16;
    const uint32_t aAl = aAh + (DSM_AL - DSM_AH);
    const uint32_t aBh = sb + DSM_BH + (warp_n >> 1) * WIMG_BYTES
                       + ((warp_n & 1) * 64 + (lane & 7) + (lane >> 4) * 8) * (KPAD * 2)
                       + ((lane >> 3) & 1) * 16;
    const uint32_t aBl = aBh + (DSM_BL - DSM_BH);

    for (int kc = 0; kc < 128; kc += 32) {
#pragma unroll
        for (int i = 0; i < 2; i++) {
            int f = tid + i * 512;
            int row = f >> 3, c4 = (f & 7) * 4;
            float4 v = pre[i];
            if (mode == 2) {
                int cc = kc + c4;
                v.x = fmaxf(0.f, fmaf(v.x, s_scale[cc],     s_shift[cc]));
                v.y = fmaxf(0.f, fmaf(v.y, s_scale[cc + 1], s_shift[cc + 1]));
                v.z = fmaxf(0.f, fmaf(v.z, s_scale[cc + 2], s_shift[cc + 2]));
                v.w = fmaxf(0.f, fmaf(v.w, s_scale[cc + 3], s_shift[cc + 3]));
            }
            *(uint2*)(smem + DSM_AH + row * APADB + c4 * 2) =
                make_uint2(pack_hi(v.x, v.y), pack_hi(v.z, v.w));
            *(uint2*)(smem + DSM_AL + row * APADB + c4 * 2) =
                make_uint2(pack_lo(v.x, v.y), pack_lo(v.z, v.w));
        }
        __syncthreads();

        if (kc < 96) {
#pragma unroll
            for (int i = 0; i < 2; i++) {
                int f = tid + i * 512;
                int row = f >> 3, c4 = (f & 7) * 4;
                int gr = row0 + row;
                pre[i] = (gr < n) ? *(const float4*)&X[(size_t)gr * 128 + kc + 32 + c4]
                                  : make_float4(0.f, 0.f, 0.f, 0.f);
            }
        }

#pragma unroll
        for (int kk = 0; kk < 32; kk += 16) {
            uint32_t ah[2][4], al[2][4];
#pragma unroll
            for (int ms = 0; ms < 2; ms++) {
                uint32_t off = ms * 16 * APADB + kk * 2;
                ldsm_x4(ah[ms][0], ah[ms][1], ah[ms][2], ah[ms][3], aAh + off);
                ldsm_x4(al[ms][0], al[ms][1], al[ms][2], al[ms][3], aAl + off);
            }
#pragma unroll
            for (int nn = 0; nn < 4; nn++) {
                uint32_t bh2[4], bl2[4];
                uint32_t off = nn * 16 * (KPAD * 2) + (kc + kk) * 2;
                ldsm_x4(bh2[0], bh2[1], bh2[2], bh2[3], aBh + off);
                ldsm_x4(bl2[0], bl2[1], bl2[2], bl2[3], aBl + off);
#pragma unroll
                for (int ms = 0; ms < 2; ms++) {
                    mma_bf16(acc[ms][nn * 2],     ah[ms], bh2);
                    mma_bf16(acc[ms][nn * 2],     al[ms], bh2);
                    mma_bf16(acc[ms][nn * 2],     ah[ms], bl2);
                    mma_bf16(acc[ms][nn * 2 + 1], ah[ms], bh2 + 2);
                    mma_bf16(acc[ms][nn * 2 + 1], al[ms], bh2 + 2);
                    mma_bf16(acc[ms][nn * 2 + 1], ah[ms], bl2 + 2);
                }
            }
        }
        if (kc < 96) __syncthreads();
    }

    float* Y = (warp_n < 2) ? YL : YR;
    const float* bias = (warp_n < 2) ? biasL : biasR;
    const int er0 = row0 + warp_m * 32 + (lane >> 2);
    const int ec0 = (warp_n & 1) * 64 + (lane & 3) * 2;
#pragma unroll
    for (int ms = 0; ms < 2; ms++) {
#pragma unroll
        for (int ns = 0; ns < 8; ns++) {
            int r = er0 + ms * 16;
            int c = ec0 + ns * 8;
            float b0 = __ldg(&bias[c]), b1 = __ldg(&bias[c + 1]);
            if (r < n)
                *(float2*)&Y[(size_t)r * 128 + c] =
                    make_float2(acc[ms][ns][0] + b0, acc[ms][ns][1] + b1);
            if (r + 8 < n)
                *(float2*)&Y[(size_t)(r + 8) * 128 + c] =
                    make_float2(acc[ms][ns][2] + b0, acc[ms][ns][3] + b1);
        }
    }
}

// ---------------- GEMM v5 (residual + fused BN stats): Y = X + X@W + b ----------------
#define SM4_AH 0
#define SM4_AL 10240
#define SM4_BH 20480
#define SM4_BL 55296
#define SM4_TOTAL 90112

__global__ __launch_bounds__(256, 2) void gemm_mma4_kernel(
    const float* __restrict__ X, int wimg, const float* __restrict__ bias,
    float* __restrict__ Y, int n)
{
    extern __shared__ char smem[];
    const uint32_t sb = smem_to_u32(smem);
    const int tid = threadIdx.x;
    const int wid = tid >> 5;
    const int lane = tid & 31;
    const int row0 = blockIdx.x * 128;
    const int warp_m = wid & 3;
    const int warp_n = wid >> 2;

    {
        const uint4* gBh = (const uint4*)(g_Wbf + (size_t)(wimg * 2 + 0) * 128 * KPAD);
        const uint4* gBl = (const uint4*)(g_Wbf + (size_t)(wimg * 2 + 1) * 128 * KPAD);
        uint4* sBh = (uint4*)(smem + SM4_BH);
        uint4* sBl = (uint4*)(smem + SM4_BL);
        for (int f = tid; f < 2176; f += 256) {
            sBh[f] = gBh[f];
            sBl[f] = gBl[f];
        }
    }

    float4 pre[4];
#pragma unroll
    for (int i = 0; i < 4; i++) {
        int f = tid + i * 256;
        int row = f >> 3, c4 = (f & 7) * 4;
        int gr = row0 + row;
        pre[i] = (gr < n) ? *(const float4*)&X[(size_t)gr * 128 + c4]
                          : make_float4(0.f, 0.f, 0.f, 0.f);
    }
    __syncthreads();

    float acc[2][8][4];
#pragma unroll
    for (int a = 0; a < 2; a++)
#pragma unroll
        for (int b = 0; b < 8; b++)
#pragma unroll
            for (int c = 0; c < 4; c++) acc[a][b][c] = 0.0f;

    const uint32_t aAh = sb + SM4_AH + (warp_m * 32 + (lane & 15)) * APADB + (lane >> 4) * 16;
    const uint32_t aAl = aAh + (SM4_AL - SM4_AH);
    const uint32_t aBh = sb + SM4_BH + (warp_n * 64 + (lane & 7) + (lane >> 4) * 8) * (KPAD * 2)
                       + ((lane >> 3) & 1) * 16;
    const uint32_t aBl = aBh + (SM4_BL - SM4_BH);

    for (int kc = 0; kc < 128; kc += 32) {
#pragma unroll
        for (int i = 0; i < 4; i++) {
            int f = tid + i * 256;
            int row = f >> 3, c4 = (f & 7) * 4;
            float4 v = pre[i];
            *(uint2*)(smem + SM4_AH + row * APADB + c4 * 2) =
                make_uint2(pack_hi(v.x, v.y), pack_hi(v.z, v.w));
            *(uint2*)(smem + SM4_AL + row * APADB + c4 * 2) =
                make_uint2(pack_lo(v.x, v.y), pack_lo(v.z, v.w));
        }
        __syncthreads();

        if (kc < 96) {
#pragma unroll
            for (int i = 0; i < 4; i++) {
                int f = tid + i * 256;
                int row = f >> 3, c4 = (f & 7) * 4;
                int gr = row0 + row;
                pre[i] = (gr < n) ? *(const float4*)&X[(size_t)gr * 128 + kc + 32 + c4]
                                  : make_float4(0.f, 0.f, 0.f, 0.f);
            }
        }

#pragma unroll
        for (int kk = 0; kk < 32; kk += 16) {
            uint32_t ah[2][4], al[2][4];
#pragma unroll
            for (int ms = 0; ms < 2; ms++) {
                uint32_t off = ms * 16 * APADB + kk * 2;
                ldsm_x4(ah[ms][0], ah[ms][1], ah[ms][2], ah[ms][3], aAh + off);
                ldsm_x4(al[ms][0], al[ms][1], al[ms][2], al[ms][3], aAl + off);
            }
#pragma unroll
            for (int nn = 0; nn < 4; nn++) {
                uint32_t bh2[4], bl2[4];
                uint32_t off = nn * 16 * (KPAD * 2) + (kc + kk) * 2;
                ldsm_x4(bh2[0], bh2[1], bh2[2], bh2[3], aBh + off);
                ldsm_x4(bl2[0], bl2[1], bl2[2], bl2[3], aBl + off);
#pragma unroll
                for (int ms = 0; ms < 2; ms++) {
                    mma_bf16(acc[ms][nn * 2],     ah[ms], bh2);
                    mma_bf16(acc[ms][nn * 2],     al[ms], bh2);
                    mma_bf16(acc[ms][nn * 2],     ah[ms], bl2);
                    mma_bf16(acc[ms][nn * 2 + 1], ah[ms], bh2 + 2);
                    mma_bf16(acc[ms][nn * 2 + 1], al[ms], bh2 + 2);
                    mma_bf16(acc[ms][nn * 2 + 1], ah[ms], bl2 + 2);
                }
            }
        }
        if (kc < 96) __syncthreads();
    }

    // epilogue with fused BN stats (column sum / sumsq)
    float cs[16], cq[16];
#pragma unroll
    for (int j = 0; j < 16; j++) { cs[j] = 0.f; cq[j] = 0.f; }

    const int er0 = row0 + warp_m * 32 + (lane >> 2);
    const int ec0 = warp_n * 64 + (lane & 3) * 2;
#pragma unroll
    for (int ms = 0; ms < 2; ms++) {
#pragma unroll
        for (int ns = 0; ns < 8; ns++) {
            int r = er0 + ms * 16;
            int c = ec0 + ns * 8;
            float b0 = __ldg(&bias[c]), b1 = __ldg(&bias[c + 1]);
            if (r < n) {
                const float2 rv = *(const float2*)&X[(size_t)r * 128 + c];
                float o0 = acc[ms][ns][0] + b0 + rv.x;
                float o1 = acc[ms][ns][1] + b1 + rv.y;
                *(float2*)&Y[(size_t)r * 128 + c] = make_float2(o0, o1);
                cs[ns * 2] += o0; cq[ns * 2] += o0 * o0;
                cs[ns * 2 + 1] += o1; cq[ns * 2 + 1] += o1 * o1;
            }
            if (r + 8 < n) {
                const float2 rv = *(const float2*)&X[(size_t)(r + 8) * 128 + c];
                float o0 = acc[ms][ns][2] + b0 + rv.x;
                float o1 = acc[ms][ns][3] + b1 + rv.y;
                *(float2*)&Y[(size_t)(r + 8) * 128 + c] = make_float2(o0, o1);
                cs[ns * 2] += o0; cq[ns * 2] += o0 * o0;
                cs[ns * 2 + 1] += o1; cq[ns * 2 + 1] += o1 * o1;
            }
        }
    }

    // stage 1: reduce across the 8 lanes sharing a column set (offsets 4,8,16)
#pragma unroll
    for (int o = 4; o <= 16; o <<= 1) {
#pragma unroll
        for (int j = 0; j < 16; j++) {
            cs[j] += __shfl_xor_sync(0xffffffff, cs[j], o);
            cq[j] += __shfl_xor_sync(0xffffffff, cq[j], o);
        }
    }
    // stage 2: per-warp partials to smem (reuse A region; all ldmatrix reads done)
    __syncthreads();
    float (*sred)[4][32] = (float (*)[4][32])(smem + SM4_AH);  // [8 warps][4 lanes][32]
    if (lane < 4) {
#pragma unroll
        for (int j = 0; j < 16; j++) {
            sred[wid][lane][j] = cs[j];
            sred[wid][lane][16 + j] = cq[j];
        }
    }
    __syncthreads();
    // stage 3: 256 threads -> 128 cols x 2 stats; sum over 4 warp_m, atomicAdd global
    {
        int stat = tid >> 7;
        int col = tid & 127;
        int wn = col >> 6;
        int lane_sel = (col >> 1) & 3;
        int nss = (col & 63) >> 3;
        int j0 = nss * 2 + (col & 1);
        int idx = stat * 16 + j0;
        float t = sred[wn * 4 + 0][lane_sel][idx] + sred[wn * 4 + 1][lane_sel][idx]
                + sred[wn * 4 + 2][lane_sel][idx] + sred[wn * 4 + 3][lane_sel][idx];
        if (stat == 0) atomicAdd(&g_sum[col], t);
        else           atomicAdd(&g_sumsq[col], t);
    }
}

// ---------------- CSR build ------------------------------------------------------
__global__ void csr_hist_kernel(const int* __restrict__ dst, int E) {
    int e = blockIdx.x * blockDim.x + threadIdx.x;
    if (e < E) atomicAdd(&g_deg[dst[e]], 1);
}
__global__ void csr_scanA_kernel(int n) {
    __shared__ int s[1024];
    int t = threadIdx.x;
    int i = blockIdx.x * 1024 + t;
    int v = (i < n) ? g_deg[i] : 0;
    s[t] = v;
    __syncthreads();
#pragma unroll
    for (int off = 1; off < 1024; off <<= 1) {
        int x = (t >= off) ? s[t - off] : 0;
        __syncthreads();
        s[t] += x;
        __syncthreads();
    }
    if (i < n) g_rowptr[i + 1] = s[t];
    if (t == 1023) g_blocksum[blockIdx.x] = s[t];
    if (i == 0) g_rowptr[0] = 0;
}
__global__ void csr_scanC_kernel(int n) {
    __shared__ int s_off;
    int t = threadIdx.x;
    if (t < 32) {
        int b = blockIdx.x;
        int sum = 0;
        for (int i = t; i < b; i += 32) sum += g_blocksum[i];
#pragma unroll
        for (int o = 16; o; o >>= 1) sum += __shfl_xor_sync(0xffffffff, sum, o);
        if (t == 0) s_off = sum;
    }
    __syncthreads();
    int i = blockIdx.x * 1024 + t;
    if (i < n) g_rowptr[i + 1] += s_off;
}
__global__ void csr_fill_kernel(const int* __restrict__ src, const int* __restrict__ dst, int E) {
    int e = blockIdx.x * blockDim.x + threadIdx.x;
    if (e < E) {
        int d = dst[e];
        int pos = g_rowptr[d] + atomicAdd(&g_fill[d], 1);
        g_col[pos] = src[e];
    }
}

// ---------------- aggregation v3: warp/node, 2-deep gather prefetch pipeline ----------
__device__ __forceinline__ float dot_leaky(float4 xs4, float4 xd4, float4 at4) {
    float t, p = 0.0f;
    t = xs4.x + xd4.x; t = t > 0.f ? t : NEG_SLOPE * t; p = fmaf(t, at4.x, p);
    t = xs4.y + xd4.y; t = t > 0.f ? t : NEG_SLOPE * t; p = fmaf(t, at4.y, p);
    t = xs4.z + xd4.z; t = t > 0.f ? t : NEG_SLOPE * t; p = fmaf(t, at4.z, p);
    t = xs4.w + xd4.w; t = t > 0.f ? t : NEG_SLOPE * t; p = fmaf(t, at4.w, p);
    return p;
}

__global__ __launch_bounds__(256) void agg_kernel(
    const float* __restrict__ att, const float* __restrict__ cb, int n)
{
    if (blockIdx.x == 0 && threadIdx.x < HDIM) {
        g_sum[threadIdx.x] = 0.0f;
        g_sumsq[threadIdx.x] = 0.0f;
    }
    int d = (blockIdx.x * blockDim.x + threadIdx.x) >> 5;
    int lane = threadIdx.x & 31;
    if (d >= n) return;

    float4 xd4 = *(const float4*)&g_xd[(size_t)d * 128 + lane * 4];
    float4 at4 = *(const float4*)&att[lane * 4];
    int e0 = g_rowptr[d], e1 = g_rowptr[d + 1];

    float den = 0.0f;
    float4 acc = make_float4(0.f, 0.f, 0.f, 0.f);

    if (e0 < e1) {
        // prologue: gather first pair
        int s0 = g_col[e0];
        int s1 = (e0 + 1 < e1) ? g_col[e0 + 1] : s0;
        float4 a0 = *(const float4*)&g_xs[(size_t)s0 * 128 + lane * 4];
        float4 a1 = *(const float4*)&g_xs[(size_t)s1 * 128 + lane * 4];

        for (int e = e0; e < e1; e += 2) {
            float4 c0 = a0, c1 = a1;
            bool v1 = (e + 1 < e1);
            // prefetch next pair's gathers; latency overlaps the chain below
            if (e + 2 < e1) {
                int t0 = g_col[e + 2];
                int t1 = (e + 3 < e1) ? g_col[e + 3] : t0;
                a0 = *(const float4*)&g_xs[(size_t)t0 * 128 + lane * 4];
                a1 = *(const float4*)&g_xs[(size_t)t1 * 128 + lane * 4];
            }
            float p0 = dot_leaky(c0, xd4, at4);
            float p1 = dot_leaky(c1, xd4, at4);
#pragma unroll
            for (int o = 16; o; o >>= 1) {
                p0 += __shfl_xor_sync(0xffffffff, p0, o);
                p1 += __shfl_xor_sync(0xffffffff, p1, o);
            }
            float w0 = __expf(p0);
            float w1 = v1 ? __expf(p1) : 0.0f;
            den += w0 + w1;
            acc.x = fmaf(w0, c0.x, fmaf(w1, c1.x, acc.x));
            acc.y = fmaf(w0, c0.y, fmaf(w1, c1.y, acc.y));
            acc.z = fmaf(w0, c0.z, fmaf(w1, c1.z, acc.z));
            acc.w = fmaf(w0, c0.w, fmaf(w1, c1.w, acc.w));
        }
    }

    float inv = 1.0f / (den + 1e-16f);
    float4 cb4 = *(const float4*)&cb[lane * 4];
    float4 o;
    o.x = acc.x * inv + cb4.x;
    o.y = acc.y * inv + cb4.y;
    o.z = acc.z * inv + cb4.z;
    o.w = acc.w * inv + cb4.w;
    *(float4*)&g_acc[(size_t)d * 128 + lane * 4] = o;
}

// ---------------- BN apply (final output) ----------------------------------------------
__global__ __launch_bounds__(256) void bn_apply_kernel(
    const float* __restrict__ gamma, const float* __restrict__ beta,
    float* __restrict__ out, int n)
{
    int i = blockIdx.x * blockDim.x + threadIdx.x;
    if (i >= n * HDIM) return;
    int h = i & 127;
    float inv_n = 1.0f / (float)n;
    float mu = g_sum[h] * inv_n;
    float var = g_sumsq[h] * inv_n - mu * mu;
    out[i] = (g_h[i] - mu) * rsqrtf(var + 1e-5f) * gamma[h] + beta[h];
}

// ---------------- host driver ---------------------------------------------------------
extern "C" void kernel_launch(void* const* d_in, const int* in_sizes, int n_in,
                              void* d_out, int out_size)
{
    const float* x     = (const float*)d_in[0];
    const int*   ei    = (const int*)  d_in[1];
    const float* Wl    = (const float*)d_in[2];
    const float* bl    = (const float*)d_in[3];
    const float* Wr    = (const float*)d_in[4];
    const float* br    = (const float*)d_in[5];
    const float* att   = (const float*)d_in[6];
    const float* cb    = (const float*)d_in[7];
    const float* Wlin  = (const float*)d_in[8];
    const float* blin  = (const float*)d_in[9];
    const float* gamma = (const float*)d_in[10];
    const float* beta  = (const float*)d_in[11];

    const int n = in_sizes[0] / HDIM;
    const int E = in_sizes[1] / 2;
    const int* src = ei;
    const int* dst = ei + E;

    void* p;
    cudaGetSymbolAddress(&p, g_acc); float* p_acc = (float*)p;
    cudaGetSymbolAddress(&p, g_xs);  float* p_xs  = (float*)p;
    cudaGetSymbolAddress(&p, g_xd);  float* p_xd  = (float*)p;
    cudaGetSymbolAddress(&p, g_h);   float* p_h   = (float*)p;

    cudaFuncSetAttribute(gemm_mma4_kernel, cudaFuncAttributeMaxDynamicSharedMemorySize,
                         SM4_TOTAL);
    cudaFuncSetAttribute(gemm_dual_kernel, cudaFuncAttributeMaxDynamicSharedMemorySize,
                         DSM_TOTAL);

    const int elem_blocks = (n * HDIM + 255) / 256;
    const int gemm_blocks = (n + 127) / 128;
    const int agg_blocks  = (n + 7) / 8;
    const int e_blocks    = (E + 255) / 256;
    const int scan_blocks = (n + 1023) / 1024;
    const int prep_blocks = (((n > 6 * 128 * 128) ? n : 6 * 128 * 128) + 255) / 256;

    prep_w_kernel<<<prep_blocks, 256>>>(Wl, Wr, Wlin, n);                         // 1
    csr_hist_kernel<<<e_blocks, 256>>>(dst, E);                                   // 2
    csr_scanA_kernel<<<scan_blocks, 1024>>>(n);                                   // 3
    gemm_dual_kernel<<<gemm_blocks, 512, DSM_TOTAL>>>(x, 0, 1, bl, br, p_xs, p_xd,
                                                      n, 0, nullptr, nullptr);    // 4 (profiled)
    csr_scanC_kernel<<<scan_blocks, 1024>>>(n);                                   // 5
    csr_fill_kernel<<<e_blocks, 256>>>(src, dst, E);                              // 6

    // layer 0
    agg_kernel<<<agg_blocks, 256>>>(att, cb, n);                                  // 7
    gemm_mma4_kernel<<<gemm_blocks, 256, SM4_TOTAL>>>(p_acc, 2, blin, p_h, n);    // 8

    // layer 1 (BN+relu of layer-0 output fused into dual A-staging)
    gemm_dual_kernel<<<gemm_blocks, 512, DSM_TOTAL>>>(p_h, 3, 4, bl + HDIM, br + HDIM,
                                                      p_xs, p_xd, n, 2, gamma, beta); // 9
    agg_kernel<<<agg_blocks, 256>>>(att + HDIM, cb + HDIM, n);                    // 10
    gemm_mma4_kernel<<<gemm_blocks, 256, SM4_TOTAL>>>(p_acc, 5, blin + HDIM, p_h, n); // 11
    bn_apply_kernel<<<elem_blocks, 256>>>(gamma + HDIM, beta + HDIM, (float*)d_out, n); // 12
}